// round 1
// baseline (speedup 1.0000x reference)
#include <cuda_runtime.h>
#include <math.h>
#include <stdint.h>

// Problem constants
#define BB   2
#define TT   2048
#define EE   1024
#define HQn  16
#define HKVn 4
#define DD   64
#define GG   4

// Derived
#define ROWS (BB*TT)            // 4096
#define Y_ELEMS  ((size_t)BB*TT*EE)              // 4,194,304
#define ATT_ELEMS ((size_t)BB*HQn*TT*TT)         // 134,217,728

// Scratch (device globals — no allocation allowed in kernel_launch)
__device__ float g_Q[ROWS * EE];          // 16 MB
__device__ float g_K[ROWS * (HKVn*DD)];   // 4 MB
__device__ float g_V[ROWS * (HKVn*DD)];   // 4 MB
__device__ float g_Y[ROWS * EE];          // 16 MB
__device__ float g_Att[ATT_ELEMS];        // 512 MB fallback (only used if out lacks att)

// ---------------------------------------------------------------------------
// SGEMM: C[M,N] = A[M,K] @ W[K,N] + bias[N], row-major, fp32
// 128x128 tile, BK=8, 256 threads, 8x8 microtile per thread.
// Requires M%128==0, N%128==0, K%8==0 (true for all our shapes).
// ---------------------------------------------------------------------------
__global__ __launch_bounds__(256) void sgemm_bias(
    const float* __restrict__ A, const float* __restrict__ W,
    const float* __restrict__ bias, float* __restrict__ C,
    int M, int N, int K)
{
    __shared__ float As[8][128];
    __shared__ float Bs[8][128];

    const int bx = blockIdx.x;           // N tile
    const int by = blockIdx.y;           // M tile
    const int tid = threadIdx.x;
    const int tx = tid & 15;
    const int ty = tid >> 4;

    const float* Ablk = A + (size_t)by * 128 * K;
    const float* Wblk = W + (size_t)bx * 128;

    const int arow = tid >> 1;           // 0..127
    const int acol = (tid & 1) * 4;      // 0 or 4
    const int brow = tid >> 5;           // 0..7
    const int bcol = (tid & 31) * 4;     // 0..124

    float acc[8][8];
#pragma unroll
    for (int i = 0; i < 8; i++)
#pragma unroll
        for (int j = 0; j < 8; j++) acc[i][j] = 0.f;

    for (int k0 = 0; k0 < K; k0 += 8) {
        float4 av = *(const float4*)(Ablk + (size_t)arow * K + k0 + acol);
        As[acol + 0][arow] = av.x;
        As[acol + 1][arow] = av.y;
        As[acol + 2][arow] = av.z;
        As[acol + 3][arow] = av.w;
        float4 bv = *(const float4*)(Wblk + (size_t)(k0 + brow) * N + bcol);
        *(float4*)&Bs[brow][bcol] = bv;
        __syncthreads();

#pragma unroll
        for (int k = 0; k < 8; k++) {
            float a[8], b[8];
            *(float4*)&a[0] = *(const float4*)&As[k][ty * 4];
            *(float4*)&a[4] = *(const float4*)&As[k][ty * 4 + 64];
            *(float4*)&b[0] = *(const float4*)&Bs[k][tx * 4];
            *(float4*)&b[4] = *(const float4*)&Bs[k][tx * 4 + 64];
#pragma unroll
            for (int i = 0; i < 8; i++)
#pragma unroll
                for (int j = 0; j < 8; j++) acc[i][j] += a[i] * b[j];
        }
        __syncthreads();
    }

    // Write with bias
#pragma unroll
    for (int ih = 0; ih < 2; ih++) {
#pragma unroll
        for (int i = 0; i < 4; i++) {
            int r = by * 128 + ih * 64 + ty * 4 + i;
#pragma unroll
            for (int jh = 0; jh < 2; jh++) {
                int c = bx * 128 + jh * 64 + tx * 4;
                float4 o;
                o.x = acc[ih * 4 + i][jh * 4 + 0] + bias[c + 0];
                o.y = acc[ih * 4 + i][jh * 4 + 1] + bias[c + 1];
                o.z = acc[ih * 4 + i][jh * 4 + 2] + bias[c + 2];
                o.w = acc[ih * 4 + i][jh * 4 + 3] + bias[c + 3];
                *(float4*)(C + (size_t)r * N + c) = o;
            }
        }
    }
}

// ---------------------------------------------------------------------------
// RoPE (in place). buf: [ROWS, nheads*64]. One thread per rotation pair.
// Grid sized exactly; no bounds check.
// ---------------------------------------------------------------------------
__global__ __launch_bounds__(256) void rope_kernel(float* __restrict__ buf, int nheads)
{
    int idx = blockIdx.x * 256 + threadIdx.x;
    int ii  = idx & 31;
    int h   = (idx >> 5) % nheads;
    int row = idx / (32 * nheads);
    int t   = row & (TT - 1);
    // theta = 10000^(-ii/32) ; log2(10000) = 13.287712379549449
    float ang = (float)(t + 1) * exp2f((float)ii * (-13.2877123795494f / 32.0f));
    float sn, cs;
    sincosf(ang, &sn, &cs);
    float* p = buf + (size_t)row * (nheads * 64) + h * 64 + ii;
    float x0 = p[0], x1 = p[32];
    p[0]  = x0 * cs - x1 * sn;
    p[32] = x1 * cs + x0 * sn;
}

// ---------------------------------------------------------------------------
// S = Q @ K^T / sqrt(D), per head, 64x64 tiles, causal blocks skipped.
// att layout: [b][g][hkv][q][k] with z = ((b*G)+g)*HKV + hkv = b*16+g*4+hkv
// q head index = hkv*G + g ; k head index = hkv
// ---------------------------------------------------------------------------
__global__ __launch_bounds__(256) void attn_scores(
    const float* __restrict__ Q, const float* __restrict__ K,
    float* __restrict__ att)
{
    const int kb = blockIdx.x;
    const int qb = blockIdx.y;
    if (kb > qb) return;
    const int z   = blockIdx.z;
    const int b   = z >> 4;
    const int g   = (z >> 2) & 3;
    const int hkv = z & 3;
    const int hq  = hkv * GG + g;

    __shared__ float Qs[64][68];  // [d][i]
    __shared__ float Ks[64][68];  // [d][j]

    const int tid  = threadIdx.x;
    const int lrow = tid >> 2;           // 0..63
    const int c0   = (tid & 3) * 16;     // 0,16,32,48

    const float* qsrc = Q + ((size_t)(b * TT + qb * 64 + lrow)) * EE + hq * 64 + c0;
    const float* ksrc = K + ((size_t)(b * TT + kb * 64 + lrow)) * (HKVn * DD) + hkv * 64 + c0;
#pragma unroll
    for (int v = 0; v < 4; v++) {
        float4 f = *(const float4*)(qsrc + v * 4);
        Qs[c0 + v * 4 + 0][lrow] = f.x;
        Qs[c0 + v * 4 + 1][lrow] = f.y;
        Qs[c0 + v * 4 + 2][lrow] = f.z;
        Qs[c0 + v * 4 + 3][lrow] = f.w;
        float4 h = *(const float4*)(ksrc + v * 4);
        Ks[c0 + v * 4 + 0][lrow] = h.x;
        Ks[c0 + v * 4 + 1][lrow] = h.y;
        Ks[c0 + v * 4 + 2][lrow] = h.z;
        Ks[c0 + v * 4 + 3][lrow] = h.w;
    }
    __syncthreads();

    const int tx = tid & 15;
    const int ty = tid >> 4;
    float acc[4][4];
#pragma unroll
    for (int i = 0; i < 4; i++)
#pragma unroll
        for (int j = 0; j < 4; j++) acc[i][j] = 0.f;

#pragma unroll 8
    for (int d = 0; d < 64; d++) {
        float4 a = *(const float4*)&Qs[d][ty * 4];
        float4 c = *(const float4*)&Ks[d][tx * 4];
        float av[4] = {a.x, a.y, a.z, a.w};
        float cv[4] = {c.x, c.y, c.z, c.w};
#pragma unroll
        for (int i = 0; i < 4; i++)
#pragma unroll
            for (int j = 0; j < 4; j++) acc[i][j] += av[i] * cv[j];
    }

    float* obase = att + ((size_t)z * TT + qb * 64) * TT + kb * 64;
#pragma unroll
    for (int i = 0; i < 4; i++) {
        float4 o;
        o.x = acc[i][0] * 0.125f;
        o.y = acc[i][1] * 0.125f;
        o.z = acc[i][2] * 0.125f;
        o.w = acc[i][3] * 0.125f;
        *(float4*)(obase + (size_t)(ty * 4 + i) * TT + tx * 4) = o;
    }
}

// ---------------------------------------------------------------------------
// Causal row softmax, in place. Writes exact 0 above diagonal so PV kernel
// needs no masking. One block per (z, q) row.
// ---------------------------------------------------------------------------
__global__ __launch_bounds__(256) void softmax_causal(float* __restrict__ att)
{
    const int q = blockIdx.x;
    const int z = blockIdx.y;
    float* row = att + ((size_t)z * TT + q) * TT;
    const int n = q + 1;
    const int tid = threadIdx.x;
    __shared__ float red[256];

    float m = -1e30f;
    for (int i = tid; i < n; i += 256) m = fmaxf(m, row[i]);
    red[tid] = m;
    __syncthreads();
    for (int s = 128; s > 0; s >>= 1) {
        if (tid < s) red[tid] = fmaxf(red[tid], red[tid + s]);
        __syncthreads();
    }
    const float M = red[0];
    __syncthreads();

    float sum = 0.f;
    for (int i = tid; i < n; i += 256) {
        float e = expf(row[i] - M);
        row[i] = e;
        sum += e;
    }
    red[tid] = sum;
    __syncthreads();
    for (int s = 128; s > 0; s >>= 1) {
        if (tid < s) red[tid] += red[tid + s];
        __syncthreads();
    }
    const float inv = 1.0f / red[0];

    for (int i = tid; i < n; i += 256) row[i] *= inv;
    for (int i = n + tid; i < TT; i += 256) row[i] = 0.f;
}

// ---------------------------------------------------------------------------
// Y = P @ V per head; writes directly into permuted layout:
// Ybuf[b][q][hkv*256 + g*64 + d]
// ---------------------------------------------------------------------------
__global__ __launch_bounds__(256) void attn_pv(
    const float* __restrict__ att, const float* __restrict__ V,
    float* __restrict__ Y)
{
    const int qb = blockIdx.x;
    const int z  = blockIdx.y;
    const int b   = z >> 4;
    const int g   = (z >> 2) & 3;
    const int hkv = z & 3;

    __shared__ float Ps[64][68];  // [k][i]
    __shared__ float Vs[64][68];  // [k][d]

    const int tid  = threadIdx.x;
    const int lrow = tid >> 2;
    const int c0   = (tid & 3) * 16;
    const int tx   = tid & 15;
    const int ty   = tid >> 4;

    float acc[4][4];
#pragma unroll
    for (int i = 0; i < 4; i++)
#pragma unroll
        for (int j = 0; j < 4; j++) acc[i][j] = 0.f;

    const float* prow = att + ((size_t)z * TT + qb * 64 + lrow) * TT;

    for (int kb = 0; kb <= qb; kb++) {
        const float* ps = prow + kb * 64 + c0;
#pragma unroll
        for (int v = 0; v < 4; v++) {
            float4 f = *(const float4*)(ps + v * 4);
            Ps[c0 + v * 4 + 0][lrow] = f.x;
            Ps[c0 + v * 4 + 1][lrow] = f.y;
            Ps[c0 + v * 4 + 2][lrow] = f.z;
            Ps[c0 + v * 4 + 3][lrow] = f.w;
        }
        const float* vs = V + ((size_t)(b * TT + kb * 64 + lrow)) * (HKVn * DD) + hkv * 64 + c0;
#pragma unroll
        for (int v = 0; v < 4; v++) {
            *(float4*)&Vs[lrow][c0 + v * 4] = *(const float4*)(vs + v * 4);
        }
        __syncthreads();

#pragma unroll 8
        for (int k = 0; k < 64; k++) {
            float4 a = *(const float4*)&Ps[k][ty * 4];
            float4 c = *(const float4*)&Vs[k][tx * 4];
            float av[4] = {a.x, a.y, a.z, a.w};
            float cv[4] = {c.x, c.y, c.z, c.w};
#pragma unroll
            for (int i = 0; i < 4; i++)
#pragma unroll
                for (int j = 0; j < 4; j++) acc[i][j] += av[i] * cv[j];
        }
        __syncthreads();
    }

    const int col0 = hkv * 256 + g * 64 + tx * 4;
#pragma unroll
    for (int i = 0; i < 4; i++) {
        int r = b * TT + qb * 64 + ty * 4 + i;
        float4 o;
        o.x = acc[i][0];
        o.y = acc[i][1];
        o.z = acc[i][2];
        o.w = acc[i][3];
        *(float4*)(Y + (size_t)r * EE + col0) = o;
    }
}

// ---------------------------------------------------------------------------
// Launch
// ---------------------------------------------------------------------------
extern "C" void kernel_launch(void* const* d_in, const int* in_sizes, int n_in,
                              void* d_out, int out_size)
{
    const float* x  = (const float*)d_in[0];
    // d_in[1] = mask (int32) — causality hardcoded
    const float* Wq = (const float*)d_in[2];
    const float* bq = (const float*)d_in[3];
    const float* Wk = (const float*)d_in[4];
    const float* bk = (const float*)d_in[5];
    const float* Wv = (const float*)d_in[6];
    const float* bv = (const float*)d_in[7];
    const float* Wo = (const float*)d_in[8];
    const float* bo = (const float*)d_in[9];
    float* out = (float*)d_out;

    float *Qb, *Kb, *Vb, *Yb, *attScratch;
    cudaGetSymbolAddress((void**)&Qb, g_Q);
    cudaGetSymbolAddress((void**)&Kb, g_K);
    cudaGetSymbolAddress((void**)&Vb, g_V);
    cudaGetSymbolAddress((void**)&Yb, g_Y);
    cudaGetSymbolAddress((void**)&attScratch, g_Att);

    float* att = ((size_t)out_size >= Y_ELEMS + ATT_ELEMS) ? (out + Y_ELEMS)
                                                           : attScratch;

    // 1) QKV projections
    sgemm_bias<<<dim3(EE / 128, ROWS / 128), 256>>>(x, Wq, bq, Qb, ROWS, EE, EE);
    sgemm_bias<<<dim3((HKVn * DD) / 128, ROWS / 128), 256>>>(x, Wk, bk, Kb, ROWS, HKVn * DD, EE);
    sgemm_bias<<<dim3((HKVn * DD) / 128, ROWS / 128), 256>>>(x, Wv, bv, Vb, ROWS, HKVn * DD, EE);

    // 2) RoPE on Q (16 heads) and K (4 heads)
    rope_kernel<<<(ROWS * HQn * 32) / 256, 256>>>(Qb, HQn);
    rope_kernel<<<(ROWS * HKVn * 32) / 256, 256>>>(Kb, HKVn);

    // 3) S = QK^T / 8 (causal lower-triangle blocks only)
    attn_scores<<<dim3(TT / 64, TT / 64, BB * HQn), 256>>>(Qb, Kb, att);

    // 4) Causal softmax in place (writes zeros above diagonal)
    softmax_causal<<<dim3(TT, BB * HQn), 256>>>(att);

    // 5) Y = P @ V  (permuted output layout for direct O projection)
    attn_pv<<<dim3(TT / 64, BB * HQn), 256>>>(att, Vb, Yb);

    // 6) Output projection -> y
    sgemm_bias<<<dim3(EE / 128, ROWS / 128), 256>>>(Yb, Wo, bo, out, ROWS, EE, EE);
}

// round 2
// speedup vs baseline: 1.2809x; 1.2809x over previous
#include <cuda_runtime.h>
#include <math.h>
#include <stdint.h>

// Problem constants
#define BB   2
#define TT   2048
#define EE   1024
#define HQn  16
#define HKVn 4
#define DD   64
#define GG   4

#define ROWS (BB*TT)            // 4096
#define Y_ELEMS  ((size_t)BB*TT*EE)              // 4,194,304
#define ATT_ELEMS ((size_t)BB*HQn*TT*TT)         // 134,217,728

// Scratch (device globals — no allocation allowed)
__device__ float g_Q[ROWS * EE];          // 16 MB
__device__ float g_K[ROWS * (HKVn*DD)];   // 4 MB
__device__ float g_V[ROWS * (HKVn*DD)];   // 4 MB
__device__ float g_Y[ROWS * EE];          // 16 MB
__device__ float g_Att[ATT_ELEMS];        // 512 MB fallback

// ---------------------------------------------------------------------------
// TF32 helpers: split fp32 into (hi, lo) tf32 pair; 3-pass mma gives ~fp32
// accuracy (dropped lo*lo term ~2^-22 relative).
// ---------------------------------------------------------------------------
__device__ __forceinline__ void split_tf32(float x, uint32_t& hi, uint32_t& lo)
{
    asm("cvt.rna.tf32.f32 %0, %1;" : "=r"(hi) : "f"(x));
    float hf = __uint_as_float(hi);
    float l = x - hf;
    asm("cvt.rna.tf32.f32 %0, %1;" : "=r"(lo) : "f"(l));
}

__device__ __forceinline__ void mma_tf32(float (&c)[4],
                                         const uint32_t a0, const uint32_t a1,
                                         const uint32_t a2, const uint32_t a3,
                                         const uint32_t b0, const uint32_t b1)
{
    asm volatile(
        "mma.sync.aligned.m16n8k8.row.col.f32.tf32.tf32.f32 "
        "{%0,%1,%2,%3}, {%4,%5,%6,%7}, {%8,%9}, {%0,%1,%2,%3};"
        : "+f"(c[0]), "+f"(c[1]), "+f"(c[2]), "+f"(c[3])
        : "r"(a0), "r"(a1), "r"(a2), "r"(a3), "r"(b0), "r"(b1));
}

// ---------------------------------------------------------------------------
// GEMM body: C[M,N] = A[M,K] @ W[K,N] + bias, tf32 3-pass.
// Block 128x128, BK=16, 256 threads, 8 warps (warp tile 64x32).
// M%128==0, N%128==0, K%16==0 required.
// ---------------------------------------------------------------------------
__device__ __forceinline__ void gemm_body(
    const float* __restrict__ A, const float* __restrict__ W,
    const float* __restrict__ bias, float* __restrict__ C,
    int M, int N, int K)
{
    __shared__ float As[128][20];   // [m][k], pad 4 -> conflict-free frag loads
    __shared__ float Bs[16][136];   // [k][n], pad 8

    const int tid  = threadIdx.x;
    const int w    = tid >> 5;
    const int lane = tid & 31;
    const int lg   = lane >> 2;     // 0..7
    const int tg   = lane & 3;      // 0..3
    const int wm   = w & 1;         // 0..1 -> 64 rows
    const int wn   = w >> 1;        // 0..3 -> 32 cols
    const int m0   = wm * 64;
    const int n0   = wn * 32;

    const int blkM = blockIdx.y * 128;
    const int blkN = blockIdx.x * 128;

    const int arow = tid >> 1;            // 0..127
    const int acol = (tid & 1) * 8;       // 0 or 8
    const int brow = tid >> 4;            // 0..15
    const int bcol = (tid & 15) * 8;      // 0..120

    float acc[4][4][4];
#pragma unroll
    for (int i = 0; i < 4; i++)
#pragma unroll
        for (int j = 0; j < 4; j++)
#pragma unroll
            for (int v = 0; v < 4; v++) acc[i][j][v] = 0.f;

    const float* Ap = A + (size_t)(blkM + arow) * K + acol;
    const float* Wp = W + (size_t)brow * N + blkN + bcol;

    float4 pfA0 = *(const float4*)(Ap);
    float4 pfA1 = *(const float4*)(Ap + 4);
    float4 pfB0 = *(const float4*)(Wp);
    float4 pfB1 = *(const float4*)(Wp + 4);

    const int niter = K / 16;
    for (int iter = 0; iter < niter; iter++) {
        *(float4*)&As[arow][acol]     = pfA0;
        *(float4*)&As[arow][acol + 4] = pfA1;
        *(float4*)&Bs[brow][bcol]     = pfB0;
        *(float4*)&Bs[brow][bcol + 4] = pfB1;
        __syncthreads();

        if (iter + 1 < niter) {
            const float* An = Ap + (iter + 1) * 16;
            const float* Wn = Wp + (size_t)(iter + 1) * 16 * N;
            pfA0 = *(const float4*)(An);
            pfA1 = *(const float4*)(An + 4);
            pfB0 = *(const float4*)(Wn);
            pfB1 = *(const float4*)(Wn + 4);
        }

#pragma unroll
        for (int kk = 0; kk < 16; kk += 8) {
            uint32_t ahi[4][4], alo[4][4], bhi[4][2], blo[4][2];
#pragma unroll
            for (int mt = 0; mt < 4; mt++) {
                const int r = m0 + mt * 16 + lg;
                split_tf32(As[r][kk + tg],          ahi[mt][0], alo[mt][0]);
                split_tf32(As[r + 8][kk + tg],      ahi[mt][1], alo[mt][1]);
                split_tf32(As[r][kk + tg + 4],      ahi[mt][2], alo[mt][2]);
                split_tf32(As[r + 8][kk + tg + 4],  ahi[mt][3], alo[mt][3]);
            }
#pragma unroll
            for (int nt = 0; nt < 4; nt++) {
                const int cc = n0 + nt * 8 + lg;
                split_tf32(Bs[kk + tg][cc],     bhi[nt][0], blo[nt][0]);
                split_tf32(Bs[kk + tg + 4][cc], bhi[nt][1], blo[nt][1]);
            }
#pragma unroll
            for (int mt = 0; mt < 4; mt++)
#pragma unroll
                for (int nt = 0; nt < 4; nt++) {
                    mma_tf32(acc[mt][nt], ahi[mt][0], ahi[mt][1], ahi[mt][2], ahi[mt][3],
                             blo[nt][0], blo[nt][1]);
                    mma_tf32(acc[mt][nt], alo[mt][0], alo[mt][1], alo[mt][2], alo[mt][3],
                             bhi[nt][0], bhi[nt][1]);
                    mma_tf32(acc[mt][nt], ahi[mt][0], ahi[mt][1], ahi[mt][2], ahi[mt][3],
                             bhi[nt][0], bhi[nt][1]);
                }
        }
        __syncthreads();
    }

#pragma unroll
    for (int mt = 0; mt < 4; mt++) {
#pragma unroll
        for (int nt = 0; nt < 4; nt++) {
            const int col = blkN + n0 + nt * 8 + 2 * tg;
            const float b0 = bias[col], b1 = bias[col + 1];
            int r0 = blkM + m0 + mt * 16 + lg;
            float2 o;
            o.x = acc[mt][nt][0] + b0; o.y = acc[mt][nt][1] + b1;
            *(float2*)(C + (size_t)r0 * N + col) = o;
            o.x = acc[mt][nt][2] + b0; o.y = acc[mt][nt][3] + b1;
            *(float2*)(C + (size_t)(r0 + 8) * N + col) = o;
        }
    }
}

__global__ __launch_bounds__(256) void sgemm_bias_tf32(
    const float* __restrict__ A, const float* __restrict__ W,
    const float* __restrict__ bias, float* __restrict__ C,
    int M, int N, int K)
{
    gemm_body(A, W, bias, C, M, N, K);
}

// Fused K+V projection (blockIdx.z selects), doubles occupancy for small-N gemms
__global__ __launch_bounds__(256) void sgemm_kv_tf32(
    const float* __restrict__ A,
    const float* __restrict__ Wk, const float* __restrict__ bk, float* __restrict__ Kout,
    const float* __restrict__ Wv, const float* __restrict__ bv, float* __restrict__ Vout)
{
    if (blockIdx.z == 0) gemm_body(A, Wk, bk, Kout, ROWS, HKVn * DD, EE);
    else                 gemm_body(A, Wv, bv, Vout, ROWS, HKVn * DD, EE);
}

// ---------------------------------------------------------------------------
// RoPE (in place). buf: [ROWS, nheads*64].
// ---------------------------------------------------------------------------
__global__ __launch_bounds__(256) void rope_kernel(float* __restrict__ buf, int nheads)
{
    int idx = blockIdx.x * 256 + threadIdx.x;
    int ii  = idx & 31;
    int h   = (idx >> 5) % nheads;
    int row = idx / (32 * nheads);
    int t   = row & (TT - 1);
    float ang = (float)(t + 1) * exp2f((float)ii * (-13.2877123795494f / 32.0f));
    float sn, cs;
    sincosf(ang, &sn, &cs);
    float* p = buf + (size_t)row * (nheads * 64) + h * 64 + ii;
    float x0 = p[0], x1 = p[32];
    p[0]  = x0 * cs - x1 * sn;
    p[32] = x1 * cs + x0 * sn;
}

// ---------------------------------------------------------------------------
// S = Q @ K^T / 8, 64x64 tiles, tf32 3-pass. 128 threads, 4 warps (32x32).
// ---------------------------------------------------------------------------
__global__ __launch_bounds__(128) void attn_scores_tf32(
    const float* __restrict__ Q, const float* __restrict__ K,
    float* __restrict__ att)
{
    const int kb = blockIdx.x;
    const int qb = blockIdx.y;
    if (kb > qb) return;
    const int z   = blockIdx.z;
    const int b   = z >> 4;
    const int g   = (z >> 2) & 3;
    const int hkv = z & 3;
    const int hq  = hkv * GG + g;

    __shared__ float Qs[64][68];   // [q][d]
    __shared__ float Ks[64][68];   // [kpos][d]

    const int tid  = threadIdx.x;
    const int lane = tid & 31;
    const int w    = tid >> 5;
    const int lg   = lane >> 2;
    const int tg   = lane & 3;
    const int m0   = (w & 1) * 32;
    const int n0   = (w >> 1) * 32;

    {
        const int lrow = tid >> 1;          // 0..63
        const int lcol = (tid & 1) * 32;    // 0 or 32
        const float* qsrc = Q + (size_t)(b * TT + qb * 64 + lrow) * EE + hq * 64 + lcol;
        const float* ksrc = K + (size_t)(b * TT + kb * 64 + lrow) * (HKVn * DD) + hkv * 64 + lcol;
#pragma unroll
        for (int v = 0; v < 8; v++) {
            *(float4*)&Qs[lrow][lcol + v * 4] = *(const float4*)(qsrc + v * 4);
            *(float4*)&Ks[lrow][lcol + v * 4] = *(const float4*)(ksrc + v * 4);
        }
    }
    __syncthreads();

    float acc[2][4][4];
#pragma unroll
    for (int i = 0; i < 2; i++)
#pragma unroll
        for (int j = 0; j < 4; j++)
#pragma unroll
            for (int v = 0; v < 4; v++) acc[i][j][v] = 0.f;

#pragma unroll
    for (int kk = 0; kk < 64; kk += 8) {
        uint32_t ahi[2][4], alo[2][4], bhi[4][2], blo[4][2];
#pragma unroll
        for (int mt = 0; mt < 2; mt++) {
            const int r = m0 + mt * 16 + lg;
            split_tf32(Qs[r][kk + tg],         ahi[mt][0], alo[mt][0]);
            split_tf32(Qs[r + 8][kk + tg],     ahi[mt][1], alo[mt][1]);
            split_tf32(Qs[r][kk + tg + 4],     ahi[mt][2], alo[mt][2]);
            split_tf32(Qs[r + 8][kk + tg + 4], ahi[mt][3], alo[mt][3]);
        }
#pragma unroll
        for (int nt = 0; nt < 4; nt++) {
            const int rr = n0 + nt * 8 + lg;
            split_tf32(Ks[rr][kk + tg],     bhi[nt][0], blo[nt][0]);
            split_tf32(Ks[rr][kk + tg + 4], bhi[nt][1], blo[nt][1]);
        }
#pragma unroll
        for (int mt = 0; mt < 2; mt++)
#pragma unroll
            for (int nt = 0; nt < 4; nt++) {
                mma_tf32(acc[mt][nt], ahi[mt][0], ahi[mt][1], ahi[mt][2], ahi[mt][3],
                         blo[nt][0], blo[nt][1]);
                mma_tf32(acc[mt][nt], alo[mt][0], alo[mt][1], alo[mt][2], alo[mt][3],
                         bhi[nt][0], bhi[nt][1]);
                mma_tf32(acc[mt][nt], ahi[mt][0], ahi[mt][1], ahi[mt][2], ahi[mt][3],
                         bhi[nt][0], bhi[nt][1]);
            }
    }

    float* obase = att + ((size_t)z * TT + qb * 64) * TT + kb * 64;
#pragma unroll
    for (int mt = 0; mt < 2; mt++)
#pragma unroll
        for (int nt = 0; nt < 4; nt++) {
            const int col = n0 + nt * 8 + 2 * tg;
            const int r0 = m0 + mt * 16 + lg;
            float2 o;
            o.x = acc[mt][nt][0] * 0.125f; o.y = acc[mt][nt][1] * 0.125f;
            *(float2*)(obase + (size_t)r0 * TT + col) = o;
            o.x = acc[mt][nt][2] * 0.125f; o.y = acc[mt][nt][3] * 0.125f;
            *(float2*)(obase + (size_t)(r0 + 8) * TT + col) = o;
        }
}

// ---------------------------------------------------------------------------
// Causal row softmax in place, zeros above diagonal.
// ---------------------------------------------------------------------------
__global__ __launch_bounds__(256) void softmax_causal(float* __restrict__ att)
{
    const int q = blockIdx.x;
    const int z = blockIdx.y;
    float* row = att + ((size_t)z * TT + q) * TT;
    const int n = q + 1;
    const int tid = threadIdx.x;
    __shared__ float red[256];

    float m = -1e30f;
    for (int i = tid; i < n; i += 256) m = fmaxf(m, row[i]);
    red[tid] = m;
    __syncthreads();
    for (int s = 128; s > 0; s >>= 1) {
        if (tid < s) red[tid] = fmaxf(red[tid], red[tid + s]);
        __syncthreads();
    }
    const float M = red[0];
    __syncthreads();

    float sum = 0.f;
    for (int i = tid; i < n; i += 256) {
        float e = __expf(row[i] - M);
        row[i] = e;
        sum += e;
    }
    red[tid] = sum;
    __syncthreads();
    for (int s = 128; s > 0; s >>= 1) {
        if (tid < s) red[tid] += red[tid + s];
        __syncthreads();
    }
    const float inv = 1.0f / red[0];

    for (int i = tid; i < n; i += 256) row[i] *= inv;
    for (int i = n + tid; i < TT; i += 256) row[i] = 0.f;
}

// ---------------------------------------------------------------------------
// Y = P @ V, tf32 3-pass. Block 64q x 64d, 128 threads, 4 warps (32x32).
// Writes permuted layout Y[b*T+q][hkv*256 + g*64 + d].
// ---------------------------------------------------------------------------
__global__ __launch_bounds__(128) void attn_pv_tf32(
    const float* __restrict__ att, const float* __restrict__ V,
    float* __restrict__ Y)
{
    const int qb = blockIdx.x;
    const int z  = blockIdx.y;
    const int b   = z >> 4;
    const int g   = (z >> 2) & 3;
    const int hkv = z & 3;

    __shared__ float Ps[64][68];  // [q][k]
    __shared__ float Vs[64][72];  // [k][d]

    const int tid  = threadIdx.x;
    const int lane = tid & 31;
    const int w    = tid >> 5;
    const int lg   = lane >> 2;
    const int tg   = lane & 3;
    const int m0   = (w & 1) * 32;
    const int n0   = (w >> 1) * 32;

    const int lrow = tid >> 1;
    const int lcol = (tid & 1) * 32;

    float acc[2][4][4];
#pragma unroll
    for (int i = 0; i < 2; i++)
#pragma unroll
        for (int j = 0; j < 4; j++)
#pragma unroll
            for (int v = 0; v < 4; v++) acc[i][j][v] = 0.f;

    const float* prow = att + ((size_t)z * TT + qb * 64 + lrow) * TT + lcol;
    const float* vsrc0 = V + (size_t)(b * TT + lrow) * (HKVn * DD) + hkv * 64 + lcol;

    for (int kb = 0; kb <= qb; kb++) {
        const float* ps = prow + kb * 64;
        const float* vs = vsrc0 + (size_t)kb * 64 * (HKVn * DD);
#pragma unroll
        for (int v = 0; v < 8; v++) {
            *(float4*)&Ps[lrow][lcol + v * 4] = *(const float4*)(ps + v * 4);
            *(float4*)&Vs[lrow][lcol + v * 4] = *(const float4*)(vs + v * 4);
        }
        __syncthreads();

#pragma unroll
        for (int kk = 0; kk < 64; kk += 8) {
            uint32_t ahi[2][4], alo[2][4], bhi[4][2], blo[4][2];
#pragma unroll
            for (int mt = 0; mt < 2; mt++) {
                const int r = m0 + mt * 16 + lg;
                split_tf32(Ps[r][kk + tg],         ahi[mt][0], alo[mt][0]);
                split_tf32(Ps[r + 8][kk + tg],     ahi[mt][1], alo[mt][1]);
                split_tf32(Ps[r][kk + tg + 4],     ahi[mt][2], alo[mt][2]);
                split_tf32(Ps[r + 8][kk + tg + 4], ahi[mt][3], alo[mt][3]);
            }
#pragma unroll
            for (int nt = 0; nt < 4; nt++) {
                const int cc = n0 + nt * 8 + lg;
                split_tf32(Vs[kk + tg][cc],     bhi[nt][0], blo[nt][0]);
                split_tf32(Vs[kk + tg + 4][cc], bhi[nt][1], blo[nt][1]);
            }
#pragma unroll
            for (int mt = 0; mt < 2; mt++)
#pragma unroll
                for (int nt = 0; nt < 4; nt++) {
                    mma_tf32(acc[mt][nt], ahi[mt][0], ahi[mt][1], ahi[mt][2], ahi[mt][3],
                             blo[nt][0], blo[nt][1]);
                    mma_tf32(acc[mt][nt], alo[mt][0], alo[mt][1], alo[mt][2], alo[mt][3],
                             bhi[nt][0], bhi[nt][1]);
                    mma_tf32(acc[mt][nt], ahi[mt][0], ahi[mt][1], ahi[mt][2], ahi[mt][3],
                             bhi[nt][0], bhi[nt][1]);
                }
        }
        __syncthreads();
    }

    const int colbase = hkv * 256 + g * 64;
#pragma unroll
    for (int mt = 0; mt < 2; mt++)
#pragma unroll
        for (int nt = 0; nt < 4; nt++) {
            const int col = colbase + n0 + nt * 8 + 2 * tg;
            const int r0 = b * TT + qb * 64 + m0 + mt * 16 + lg;
            float2 o;
            o.x = acc[mt][nt][0]; o.y = acc[mt][nt][1];
            *(float2*)(Y + (size_t)r0 * EE + col) = o;
            o.x = acc[mt][nt][2]; o.y = acc[mt][nt][3];
            *(float2*)(Y + (size_t)(r0 + 8) * EE + col) = o;
        }
}

// ---------------------------------------------------------------------------
// Launch
// ---------------------------------------------------------------------------
extern "C" void kernel_launch(void* const* d_in, const int* in_sizes, int n_in,
                              void* d_out, int out_size)
{
    const float* x  = (const float*)d_in[0];
    const float* Wq = (const float*)d_in[2];
    const float* bq = (const float*)d_in[3];
    const float* Wk = (const float*)d_in[4];
    const float* bk = (const float*)d_in[5];
    const float* Wv = (const float*)d_in[6];
    const float* bv = (const float*)d_in[7];
    const float* Wo = (const float*)d_in[8];
    const float* bo = (const float*)d_in[9];
    float* out = (float*)d_out;

    float *Qb, *Kb, *Vb, *Yb, *attScratch;
    cudaGetSymbolAddress((void**)&Qb, g_Q);
    cudaGetSymbolAddress((void**)&Kb, g_K);
    cudaGetSymbolAddress((void**)&Vb, g_V);
    cudaGetSymbolAddress((void**)&Yb, g_Y);
    cudaGetSymbolAddress((void**)&attScratch, g_Att);

    float* att = ((size_t)out_size >= Y_ELEMS + ATT_ELEMS) ? (out + Y_ELEMS)
                                                           : attScratch;

    // 1) Q projection + fused K/V projections
    sgemm_bias_tf32<<<dim3(EE / 128, ROWS / 128), 256>>>(x, Wq, bq, Qb, ROWS, EE, EE);
    sgemm_kv_tf32<<<dim3((HKVn * DD) / 128, ROWS / 128, 2), 256>>>(x, Wk, bk, Kb, Wv, bv, Vb);

    // 2) RoPE
    rope_kernel<<<(ROWS * HQn * 32) / 256, 256>>>(Qb, HQn);
    rope_kernel<<<(ROWS * HKVn * 32) / 256, 256>>>(Kb, HKVn);

    // 3) S = QK^T / 8 (lower-triangle blocks)
    attn_scores_tf32<<<dim3(TT / 64, TT / 64, BB * HQn), 128>>>(Qb, Kb, att);

    // 4) Softmax (zeros above diagonal)
    softmax_causal<<<dim3(TT, BB * HQn), 256>>>(att);

    // 5) Y = P @ V
    attn_pv_tf32<<<dim3(TT / 64, BB * HQn), 128>>>(att, Vb, Yb);

    // 6) Output projection
    sgemm_bias_tf32<<<dim3(EE / 128, ROWS / 128), 256>>>(Yb, Wo, bo, out, ROWS, EE, EE);
}

// round 3
// speedup vs baseline: 1.3411x; 1.0470x over previous
#include <cuda_runtime.h>
#include <math.h>
#include <stdint.h>

#define BB   2
#define TT   2048
#define EE   1024
#define HQn  16
#define HKVn 4
#define DD   64
#define GG   4

#define ROWS (BB*TT)
#define KVW  (HKVn*DD)
#define Y_ELEMS  ((size_t)BB*TT*EE)
#define ATT_ELEMS ((size_t)BB*HQn*TT*TT)

__device__ float g_Q [ROWS * EE];
__device__ float g_K [ROWS * KVW];
__device__ float g_V [ROWS * KVW];
__device__ float g_Y [ROWS * EE];
__device__ float g_Att[ATT_ELEMS];

__device__ float g_xh[ROWS * EE];
__device__ float g_xl[ROWS * EE];
__device__ float g_Qh[ROWS * EE];
__device__ float g_Ql[ROWS * EE];
__device__ float g_Kh[ROWS * KVW];
__device__ float g_Kl[ROWS * KVW];
__device__ float g_Vh[ROWS * KVW];
__device__ float g_Yh[ROWS * EE];
__device__ float g_Yl[ROWS * EE];
__device__ float g_Wqh[EE * EE];
__device__ float g_Wkh[EE * KVW];
__device__ float g_Wvh[EE * KVW];
__device__ float g_Woh[EE * EE];

__device__ __forceinline__ float tf32r(float x)
{
    uint32_t u;
    asm("cvt.rna.tf32.f32 %0, %1;" : "=r"(u) : "f"(x));
    return __uint_as_float(u);
}

__device__ __forceinline__ void mma_tf32(float (&c)[4],
                                         uint32_t a0, uint32_t a1,
                                         uint32_t a2, uint32_t a3,
                                         uint32_t b0, uint32_t b1)
{
    asm volatile(
        "mma.sync.aligned.m16n8k8.row.col.f32.tf32.tf32.f32 "
        "{%0,%1,%2,%3}, {%4,%5,%6,%7}, {%8,%9}, {%0,%1,%2,%3};"
        : "+f"(c[0]), "+f"(c[1]), "+f"(c[2]), "+f"(c[3])
        : "r"(a0), "r"(a1), "r"(a2), "r"(a3), "r"(b0), "r"(b1));
}

__global__ __launch_bounds__(256) void split2_kernel(
    const float4* __restrict__ src, float4* __restrict__ hi,
    float4* __restrict__ lo, int n4)
{
    int i = blockIdx.x * 256 + threadIdx.x;
    if (i >= n4) return;
    float4 v = src[i];
    float4 h, l;
    h.x = tf32r(v.x); l.x = tf32r(v.x - h.x);
    h.y = tf32r(v.y); l.y = tf32r(v.y - h.y);
    h.z = tf32r(v.z); l.z = tf32r(v.z - h.z);
    h.w = tf32r(v.w); l.w = tf32r(v.w - h.w);
    hi[i] = h; lo[i] = l;
}

__global__ __launch_bounds__(256) void split1_kernel(
    const float4* __restrict__ src, float4* __restrict__ hi, int n4)
{
    int i = blockIdx.x * 256 + threadIdx.x;
    if (i >= n4) return;
    float4 v = src[i];
    float4 h;
    h.x = tf32r(v.x); h.y = tf32r(v.y); h.z = tf32r(v.z); h.w = tf32r(v.w);
    hi[i] = h;
}

__device__ __forceinline__ void gemm2p_body(
    const float* __restrict__ Ah, const float* __restrict__ Al,
    const float* __restrict__ Bh, const float* __restrict__ bias,
    float* __restrict__ C, int M, int N, int K)
{
    __shared__ float sAh[128][20];
    __shared__ float sAl[128][20];
    __shared__ float sBh[16][136];

    const int tid  = threadIdx.x;
    const int w    = tid >> 5;
    const int lane = tid & 31;
    const int lg   = lane >> 2;
    const int tg   = lane & 3;
    const int m0   = (w & 1) * 64;
    const int n0   = (w >> 1) * 32;

    const int blkM = blockIdx.y * 128;
    const int blkN = blockIdx.x * 128;

    const int arow = tid >> 1;
    const int acol = (tid & 1) * 8;
    const int brow = tid >> 4;
    const int bcol = (tid & 15) * 8;

    float acc[4][4][4];
#pragma unroll
    for (int i = 0; i < 4; i++)
#pragma unroll
        for (int j = 0; j < 4; j++)
#pragma unroll
            for (int v = 0; v < 4; v++) acc[i][j][v] = 0.f;

    const float* Ahp = Ah + (size_t)(blkM + arow) * K + acol;
    const float* Alp = Al + (size_t)(blkM + arow) * K + acol;
    const float* Bp  = Bh + (size_t)brow * N + blkN + bcol;

    float4 pAh0 = *(const float4*)(Ahp);
    float4 pAh1 = *(const float4*)(Ahp + 4);
    float4 pAl0 = *(const float4*)(Alp);
    float4 pAl1 = *(const float4*)(Alp + 4);
    float4 pB0  = *(const float4*)(Bp);
    float4 pB1  = *(const float4*)(Bp + 4);

    const int niter = K / 16;
    for (int iter = 0; iter < niter; iter++) {
        *(float4*)&sAh[arow][acol]     = pAh0;
        *(float4*)&sAh[arow][acol + 4] = pAh1;
        *(float4*)&sAl[arow][acol]     = pAl0;
        *(float4*)&sAl[arow][acol + 4] = pAl1;
        *(float4*)&sBh[brow][bcol]     = pB0;
        *(float4*)&sBh[brow][bcol + 4] = pB1;
        __syncthreads();

        if (iter + 1 < niter) {
            const float* a0 = Ahp + (iter + 1) * 16;
            const float* a1 = Alp + (iter + 1) * 16;
            const float* b  = Bp  + (size_t)(iter + 1) * 16 * N;
            pAh0 = *(const float4*)(a0);
            pAh1 = *(const float4*)(a0 + 4);
            pAl0 = *(const float4*)(a1);
            pAl1 = *(const float4*)(a1 + 4);
            pB0  = *(const float4*)(b);
            pB1  = *(const float4*)(b + 4);
        }

#pragma unroll
        for (int kk = 0; kk < 16; kk += 8) {
            uint32_t ah[4][4], al[4][4], bh[4][2];
#pragma unroll
            for (int mt = 0; mt < 4; mt++) {
                const int r = m0 + mt * 16 + lg;
                ah[mt][0] = __float_as_uint(sAh[r][kk + tg]);
                ah[mt][1] = __float_as_uint(sAh[r + 8][kk + tg]);
                ah[mt][2] = __float_as_uint(sAh[r][kk + tg + 4]);
                ah[mt][3] = __float_as_uint(sAh[r + 8][kk + tg + 4]);
                al[mt][0] = __float_as_uint(sAl[r][kk + tg]);
                al[mt][1] = __float_as_uint(sAl[r + 8][kk + tg]);
                al[mt][2] = __float_as_uint(sAl[r][kk + tg + 4]);
                al[mt][3] = __float_as_uint(sAl[r + 8][kk + tg + 4]);
            }
#pragma unroll
            for (int nt = 0; nt < 4; nt++) {
                const int cc = n0 + nt * 8 + lg;
                bh[nt][0] = __float_as_uint(sBh[kk + tg][cc]);
                bh[nt][1] = __float_as_uint(sBh[kk + tg + 4][cc]);
            }
#pragma unroll
            for (int mt = 0; mt < 4; mt++)
#pragma unroll
                for (int nt = 0; nt < 4; nt++) {
                    mma_tf32(acc[mt][nt], ah[mt][0], ah[mt][1], ah[mt][2], ah[mt][3],
                             bh[nt][0], bh[nt][1]);
                    mma_tf32(acc[mt][nt], al[mt][0], al[mt][1], al[mt][2], al[mt][3],
                             bh[nt][0], bh[nt][1]);
                }
        }
        __syncthreads();
    }

#pragma unroll
    for (int mt = 0; mt < 4; mt++)
#pragma unroll
        for (int nt = 0; nt < 4; nt++) {
            const int col = blkN + n0 + nt * 8 + 2 * tg;
            const float b0 = bias[col], b1 = bias[col + 1];
            int r0 = blkM + m0 + mt * 16 + lg;
            float2 o;
            o.x = acc[mt][nt][0] + b0; o.y = acc[mt][nt][1] + b1;
            *(float2*)(C + (size_t)r0 * N + col) = o;
            o.x = acc[mt][nt][2] + b0; o.y = acc[mt][nt][3] + b1;
            *(float2*)(C + (size_t)(r0 + 8) * N + col) = o;
        }
}

__global__ __launch_bounds__(256) void sgemm2p(
    const float* __restrict__ Ah, const float* __restrict__ Al,
    const float* __restrict__ Bh, const float* __restrict__ bias,
    float* __restrict__ C, int M, int N, int K)
{
    gemm2p_body(Ah, Al, Bh, bias, C, M, N, K);
}

__global__ __launch_bounds__(256) void sgemm2p_kv(
    const float* __restrict__ Ah, const float* __restrict__ Al,
    const float* __restrict__ Wkh, const float* __restrict__ bk, float* __restrict__ Kout,
    const float* __restrict__ Wvh, const float* __restrict__ bv, float* __restrict__ Vout)
{
    if (blockIdx.z == 0) gemm2p_body(Ah, Al, Wkh, bk, Kout, ROWS, KVW, EE);
    else                 gemm2p_body(Ah, Al, Wvh, bv, Vout, ROWS, KVW, EE);
}

__global__ __launch_bounds__(256) void rope_split(
    const float* __restrict__ buf, float* __restrict__ hi,
    float* __restrict__ lo, int nheads)
{
    int idx = blockIdx.x * 256 + threadIdx.x;
    int ii  = idx & 31;
    int h   = (idx >> 5) % nheads;
    int row = idx / (32 * nheads);
    int t   = row & (TT - 1);
    float ang = (float)(t + 1) * exp2f((float)ii * (-13.2877123795494f / 32.0f));
    float sn, cs;
    sincosf(ang, &sn, &cs);
    size_t off = (size_t)row * (nheads * 64) + h * 64 + ii;
    float x0 = buf[off], x1 = buf[off + 32];
    float y0 = x0 * cs - x1 * sn;
    float y1 = x1 * cs + x0 * sn;
    float h0 = tf32r(y0), h1 = tf32r(y1);
    hi[off]      = h0;
    hi[off + 32] = h1;
    lo[off]      = tf32r(y0 - h0);
    lo[off + 32] = tf32r(y1 - h1);
}

__global__ __launch_bounds__(128) void attn_scores2p(
    const float* __restrict__ Qh, const float* __restrict__ Ql,
    const float* __restrict__ Kh, float* __restrict__ att)
{
    const int kb = blockIdx.x;
    const int qb = blockIdx.y;
    if (kb > qb) return;
    const int z   = blockIdx.z;
    const int b   = z >> 4;
    const int g   = (z >> 2) & 3;
    const int hkv = z & 3;
    const int hq  = hkv * GG + g;

    extern __shared__ float smem[];
    float (*sQh)[68] = (float(*)[68])smem;
    float (*sQl)[68] = (float(*)[68])(smem + 64 * 68);
    float (*sKh)[68] = (float(*)[68])(smem + 2 * 64 * 68);

    const int tid  = threadIdx.x;
    const int lane = tid & 31;
    const int w    = tid >> 5;
    const int lg   = lane >> 2;
    const int tg   = lane & 3;
    const int m0   = (w & 1) * 32;
    const int n0   = (w >> 1) * 32;

    {
        const int lrow = tid >> 1;
        const int lcol = (tid & 1) * 32;
        const float* qh = Qh + (size_t)(b * TT + qb * 64 + lrow) * EE + hq * 64 + lcol;
        const float* ql = Ql + (size_t)(b * TT + qb * 64 + lrow) * EE + hq * 64 + lcol;
        const float* kh = Kh + (size_t)(b * TT + kb * 64 + lrow) * KVW + hkv * 64 + lcol;
#pragma unroll
        for (int v = 0; v < 8; v++) {
            *(float4*)&sQh[lrow][lcol + v * 4] = *(const float4*)(qh + v * 4);
            *(float4*)&sQl[lrow][lcol + v * 4] = *(const float4*)(ql + v * 4);
            *(float4*)&sKh[lrow][lcol + v * 4] = *(const float4*)(kh + v * 4);
        }
    }
    __syncthreads();

    float acc[2][4][4];
#pragma unroll
    for (int i = 0; i < 2; i++)
#pragma unroll
        for (int j = 0; j < 4; j++)
#pragma unroll
            for (int v = 0; v < 4; v++) acc[i][j][v] = 0.f;

#pragma unroll
    for (int kk = 0; kk < 64; kk += 8) {
        uint32_t ah[2][4], al[2][4], bh[4][2];
#pragma unroll
        for (int mt = 0; mt < 2; mt++) {
            const int r = m0 + mt * 16 + lg;
            ah[mt][0] = __float_as_uint(sQh[r][kk + tg]);
            ah[mt][1] = __float_as_uint(sQh[r + 8][kk + tg]);
            ah[mt][2] = __float_as_uint(sQh[r][kk + tg + 4]);
            ah[mt][3] = __float_as_uint(sQh[r + 8][kk + tg + 4]);
            al[mt][0] = __float_as_uint(sQl[r][kk + tg]);
            al[mt][1] = __float_as_uint(sQl[r + 8][kk + tg]);
            al[mt][2] = __float_as_uint(sQl[r][kk + tg + 4]);
            al[mt][3] = __float_as_uint(sQl[r + 8][kk + tg + 4]);
        }
#pragma unroll
        for (int nt = 0; nt < 4; nt++) {
            const int rr = n0 + nt * 8 + lg;
            bh[nt][0] = __float_as_uint(sKh[rr][kk + tg]);
            bh[nt][1] = __float_as_uint(sKh[rr][kk + tg + 4]);
        }
#pragma unroll
        for (int mt = 0; mt < 2; mt++)
#pragma unroll
            for (int nt = 0; nt < 4; nt++) {
                mma_tf32(acc[mt][nt], ah[mt][0], ah[mt][1], ah[mt][2], ah[mt][3],
                         bh[nt][0], bh[nt][1]);
                mma_tf32(acc[mt][nt], al[mt][0], al[mt][1], al[mt][2], al[mt][3],
                         bh[nt][0], bh[nt][1]);
            }
    }

    float* obase = att + ((size_t)z * TT + qb * 64) * TT + kb * 64;
#pragma unroll
    for (int mt = 0; mt < 2; mt++)
#pragma unroll
        for (int nt = 0; nt < 4; nt++) {
            const int col = n0 + nt * 8 + 2 * tg;
            const int r0 = m0 + mt * 16 + lg;
            float2 o;
            o.x = acc[mt][nt][0] * 0.125f; o.y = acc[mt][nt][1] * 0.125f;
            *(float2*)(obase + (size_t)r0 * TT + col) = o;
            o.x = acc[mt][nt][2] * 0.125f; o.y = acc[mt][nt][3] * 0.125f;
            *(float2*)(obase + (size_t)(r0 + 8) * TT + col) = o;
        }
}

__device__ __forceinline__ float warpReduceMax(float v)
{
#pragma unroll
    for (int o = 16; o > 0; o >>= 1) v = fmaxf(v, __shfl_xor_sync(0xffffffffu, v, o));
    return v;
}
__device__ __forceinline__ float warpReduceSum(float v)
{
#pragma unroll
    for (int o = 16; o > 0; o >>= 1) v += __shfl_xor_sync(0xffffffffu, v, o);
    return v;
}

__global__ __launch_bounds__(256) void softmax_reg(float* __restrict__ att)
{
    const int q = blockIdx.x;
    const int z = blockIdx.y;
    float* row = att + ((size_t)z * TT + q) * TT;
    const int n = q + 1;
    const int tid = threadIdx.x;
    __shared__ float red[8];

    float r[8];
    float m = -1e30f;
#pragma unroll
    for (int it = 0; it < 8; it++) {
        int idx = tid + it * 256;
        r[it] = (idx < n) ? row[idx] : -1e30f;
        m = fmaxf(m, r[it]);
    }
    m = warpReduceMax(m);
    if ((tid & 31) == 0) red[tid >> 5] = m;
    __syncthreads();
    float M;
    {
        float v = (tid < 8) ? red[tid] : -1e30f;
        v = warpReduceMax(v);
        M = __shfl_sync(0xffffffffu, v, 0);
        if (tid == 0) red[0] = v;
    }
    __syncthreads();
    M = red[0];
    __syncthreads();

    float s = 0.f;
#pragma unroll
    for (int it = 0; it < 8; it++) {
        int idx = tid + it * 256;
        float e = (idx < n) ? __expf(r[it] - M) : 0.f;
        r[it] = e;
        s += e;
    }
    s = warpReduceSum(s);
    if ((tid & 31) == 0) red[tid >> 5] = s;
    __syncthreads();
    {
        float v = (tid < 8) ? red[tid] : 0.f;
        v = warpReduceSum(v);
        if (tid == 0) red[0] = v;
    }
    __syncthreads();
    const float inv = 1.0f / red[0];

#pragma unroll
    for (int it = 0; it < 8; it++) {
        int idx = tid + it * 256;
        row[idx] = r[it] * inv;
    }
}

__global__ __launch_bounds__(128) void attn_pv2p(
    const float* __restrict__ att, const float* __restrict__ Vh,
    float* __restrict__ Y)
{
    const int qb = blockIdx.x;
    const int z  = blockIdx.y;
    const int b   = z >> 4;
    const int g   = (z >> 2) & 3;
    const int hkv = z & 3;

    extern __shared__ float smem[];
    float (*sPh)[68] = (float(*)[68])smem;
    float (*sPl)[68] = (float(*)[68])(smem + 64 * 68);
    float (*sVh)[72] = (float(*)[72])(smem + 2 * 64 * 68);

    const int tid  = threadIdx.x;
    const int lane = tid & 31;
    const int w    = tid >> 5;
    const int lg   = lane >> 2;
    const int tg   = lane & 3;
    const int m0   = (w & 1) * 32;
    const int n0   = (w >> 1) * 32;

    const int lrow = tid >> 1;
    const int lcol = (tid & 1) * 32;

    float acc[2][4][4];
#pragma unroll
    for (int i = 0; i < 2; i++)
#pragma unroll
        for (int j = 0; j < 4; j++)
#pragma unroll
            for (int v = 0; v < 4; v++) acc[i][j][v] = 0.f;

    const float* prow = att + ((size_t)z * TT + qb * 64 + lrow) * TT + lcol;
    const float* vsrc0 = Vh + (size_t)(b * TT + lrow) * KVW + hkv * 64 + lcol;

    for (int kb = 0; kb <= qb; kb++) {
        const float* ps = prow + kb * 64;
        const float* vs = vsrc0 + (size_t)kb * 64 * KVW;
#pragma unroll
        for (int v = 0; v < 8; v++) {
            float4 p = *(const float4*)(ps + v * 4);
            float4 h, l;
            h.x = tf32r(p.x); l.x = tf32r(p.x - h.x);
            h.y = tf32r(p.y); l.y = tf32r(p.y - h.y);
            h.z = tf32r(p.z); l.z = tf32r(p.z - h.z);
            h.w = tf32r(p.w); l.w = tf32r(p.w - h.w);
            *(float4*)&sPh[lrow][lcol + v * 4] = h;
            *(float4*)&sPl[lrow][lcol + v * 4] = l;
            *(float4*)&sVh[lrow][lcol + v * 4] = *(const float4*)(vs + v * 4);
        }
        __syncthreads();

#pragma unroll
        for (int kk = 0; kk < 64; kk += 8) {
            uint32_t ah[2][4], al[2][4], bh[4][2];
#pragma unroll
            for (int mt = 0; mt < 2; mt++) {
                const int r = m0 + mt * 16 + lg;
                ah[mt][0] = __float_as_uint(sPh[r][kk + tg]);
                ah[mt][1] = __float_as_uint(sPh[r + 8][kk + tg]);
                ah[mt][2] = __float_as_uint(sPh[r][kk + tg + 4]);
                ah[mt][3] = __float_as_uint(sPh[r + 8][kk + tg + 4]);
                al[mt][0] = __float_as_uint(sPl[r][kk + tg]);
                al[mt][1] = __float_as_uint(sPl[r + 8][kk + tg]);
                al[mt][2] = __float_as_uint(sPl[r][kk + tg + 4]);
                al[mt][3] = __float_as_uint(sPl[r + 8][kk + tg + 4]);
            }
#pragma unroll
            for (int nt = 0; nt < 4; nt++) {
                const int cc = n0 + nt * 8 + lg;
                bh[nt][0] = __float_as_uint(sVh[kk + tg][cc]);
                bh[nt][1] = __float_as_uint(sVh[kk + tg + 4][cc]);
            }
#pragma unroll
            for (int mt = 0; mt < 2; mt++)
#pragma unroll
                for (int nt = 0; nt < 4; nt++) {
                    mma_tf32(acc[mt][nt], ah[mt][0], ah[mt][1], ah[mt][2], ah[mt][3],
                             bh[nt][0], bh[nt][1]);
                    mma_tf32(acc[mt][nt], al[mt][0], al[mt][1], al[mt][2], al[mt][3],
                             bh[nt][0], bh[nt][1]);
                }
        }
        __syncthreads();
    }

    const int colbase = hkv * 256 + g * 64;
#pragma unroll
    for (int mt = 0; mt < 2; mt++)
#pragma unroll
        for (int nt = 0; nt < 4; nt++) {
            const int col = colbase + n0 + nt * 8 + 2 * tg;
            const int r0 = b * TT + qb * 64 + m0 + mt * 16 + lg;
            float2 o;
            o.x = acc[mt][nt][0]; o.y = acc[mt][nt][1];
            *(float2*)(Y + (size_t)r0 * EE + col) = o;
            o.x = acc[mt][nt][2]; o.y = acc[mt][nt][3];
            *(float2*)(Y + (size_t)(r0 + 8) * EE + col) = o;
        }
}

extern "C" void kernel_launch(void* const* d_in, const int* in_sizes, int n_in,
                              void* d_out, int out_size)
{
    const float* x  = (const float*)d_in[0];
    const float* Wq = (const float*)d_in[2];
    const float* bq = (const float*)d_in[3];
    const float* Wk = (const float*)d_in[4];
    const float* bk = (const float*)d_in[5];
    const float* Wv = (const float*)d_in[6];
    const float* bv = (const float*)d_in[7];
    const float* Wo = (const float*)d_in[8];
    const float* bo = (const float*)d_in[9];
    float* out = (float*)d_out;

    float *Qb, *Kb, *Vb, *Yb, *attScratch;
    float *xh, *xl, *Qh, *Ql, *Kh, *Kl, *Vh, *Yh, *Yl;
    float *Wqh, *Wkh, *Wvh, *Woh;
    cudaGetSymbolAddress((void**)&Qb, g_Q);
    cudaGetSymbolAddress((void**)&Kb, g_K);
    cudaGetSymbolAddress((void**)&Vb, g_V);
    cudaGetSymbolAddress((void**)&Yb, g_Y);
    cudaGetSymbolAddress((void**)&attScratch, g_Att);
    cudaGetSymbolAddress((void**)&xh, g_xh);
    cudaGetSymbolAddress((void**)&xl, g_xl);
    cudaGetSymbolAddress((void**)&Qh, g_Qh);
    cudaGetSymbolAddress((void**)&Ql, g_Ql);
    cudaGetSymbolAddress((void**)&Kh, g_Kh);
    cudaGetSymbolAddress((void**)&Kl, g_Kl);
    cudaGetSymbolAddress((void**)&Vh, g_Vh);
    cudaGetSymbolAddress((void**)&Yh, g_Yh);
    cudaGetSymbolAddress((void**)&Yl, g_Yl);
    cudaGetSymbolAddress((void**)&Wqh, g_Wqh);
    cudaGetSymbolAddress((void**)&Wkh, g_Wkh);
    cudaGetSymbolAddress((void**)&Wvh, g_Wvh);
    cudaGetSymbolAddress((void**)&Woh, g_Woh);

    float* att = ((size_t)out_size >= Y_ELEMS + ATT_ELEMS) ? (out + Y_ELEMS)
                                                           : attScratch;

    const int SMEM_SC = (3 * 64 * 68) * 4;
    const int SMEM_PV = (2 * 64 * 68 + 64 * 72) * 4;
    cudaFuncSetAttribute(attn_scores2p, cudaFuncAttributeMaxDynamicSharedMemorySize, SMEM_SC);
    cudaFuncSetAttribute(attn_pv2p,    cudaFuncAttributeMaxDynamicSharedMemorySize, SMEM_PV);

    split2_kernel<<<(ROWS * EE / 4 + 255) / 256, 256>>>((const float4*)x, (float4*)xh, (float4*)xl, ROWS * EE / 4);
    split1_kernel<<<(EE * EE / 4 + 255) / 256, 256>>>((const float4*)Wq, (float4*)Wqh, EE * EE / 4);
    split1_kernel<<<(EE * KVW / 4 + 255) / 256, 256>>>((const float4*)Wk, (float4*)Wkh, EE * KVW / 4);
    split1_kernel<<<(EE * KVW / 4 + 255) / 256, 256>>>((const float4*)Wv, (float4*)Wvh, EE * KVW / 4);
    split1_kernel<<<(EE * EE / 4 + 255) / 256, 256>>>((const float4*)Wo, (float4*)Woh, EE * EE / 4);

    sgemm2p<<<dim3(EE / 128, ROWS / 128), 256>>>(xh, xl, Wqh, bq, Qb, ROWS, EE, EE);
    sgemm2p_kv<<<dim3(KVW / 128, ROWS / 128, 2), 256>>>(xh, xl, Wkh, bk, Kb, Wvh, bv, Vb);

    rope_split<<<(ROWS * HQn * 32) / 256, 256>>>(Qb, Qh, Ql, HQn);
    rope_split<<<(ROWS * HKVn * 32) / 256, 256>>>(Kb, Kh, Kl, HKVn);
    split1_kernel<<<(ROWS * KVW / 4 + 255) / 256, 256>>>((const float4*)Vb, (float4*)Vh, ROWS * KVW / 4);

    attn_scores2p<<<dim3(TT / 64, TT / 64, BB * HQn), 128, SMEM_SC>>>(Qh, Ql, Kh, att);

    softmax_reg<<<dim3(TT, BB * HQn), 256>>>(att);

    attn_pv2p<<<dim3(TT / 64, BB * HQn), 128, SMEM_PV>>>(att, Vh, Yb);

    split2_kernel<<<(ROWS * EE / 4 + 255) / 256, 256>>>((const float4*)Yb, (float4*)Yh, (float4*)Yl, ROWS * EE / 4);
    sgemm2p<<<dim3(EE / 128, ROWS / 128), 256>>>(Yh, Yl, Woh, bo, out, ROWS, EE, EE);
}

// round 4
// speedup vs baseline: 1.9917x; 1.4851x over previous
#include <cuda_runtime.h>
#include <cuda_bf16.h>
#include <math.h>
#include <stdint.h>

#define BB   2
#define TT   2048
#define EE   1024
#define HQn  16
#define HKVn 4
#define DD   64
#define GG   4

#define ROWS (BB*TT)
#define KVW  (HKVn*DD)
#define Y_ELEMS  ((size_t)BB*TT*EE)
#define ATT_ELEMS ((size_t)BB*HQn*TT*TT)

typedef __nv_bfloat16 bf16;

// ---------------- device scratch ----------------
__device__ float g_Q[ROWS * EE];
__device__ float g_K[ROWS * KVW];
__device__ float g_V[ROWS * KVW];
__device__ float g_Att[ATT_ELEMS];

__device__ bf16 g_xh[ROWS * EE],  g_xl[ROWS * EE];
__device__ bf16 g_Qh[ROWS * EE],  g_Ql[ROWS * EE];
__device__ bf16 g_Kh[ROWS * KVW], g_Kl[ROWS * KVW];
__device__ bf16 g_Vth[BB * KVW * TT], g_Vtl[BB * KVW * TT];   // [(b*4+hkv)*64+d][t]
__device__ bf16 g_Yh[ROWS * EE],  g_Yl[ROWS * EE];
__device__ bf16 g_Wqth[EE * EE],  g_Wqtl[EE * EE];            // [N][K]
__device__ bf16 g_Wkth[EE * KVW], g_Wktl[EE * KVW];
__device__ bf16 g_Wvth[EE * KVW], g_Wvtl[EE * KVW];
__device__ bf16 g_Woth[EE * EE],  g_Wotl[EE * EE];

// ---------------- helpers ----------------
__device__ __forceinline__ void bsplit(float x, bf16& h, bf16& l)
{
    h = __float2bfloat16_rn(x);
    l = __float2bfloat16_rn(x - __bfloat162float(h));
}

__device__ __forceinline__ void mma_bf16(float (&c)[4],
                                         uint32_t a0, uint32_t a1,
                                         uint32_t a2, uint32_t a3,
                                         uint32_t b0, uint32_t b1)
{
    asm volatile(
        "mma.sync.aligned.m16n8k16.row.col.f32.bf16.bf16.f32 "
        "{%0,%1,%2,%3}, {%4,%5,%6,%7}, {%8,%9}, {%0,%1,%2,%3};"
        : "+f"(c[0]), "+f"(c[1]), "+f"(c[2]), "+f"(c[3])
        : "r"(a0), "r"(a1), "r"(a2), "r"(a3), "r"(b0), "r"(b1));
}

// ---------------- preprocessing kernels ----------------
// W [K][N] fp32 -> Wt [N][K] bf16 hi/lo
__global__ __launch_bounds__(256) void wtrans_split(
    const float* __restrict__ W, bf16* __restrict__ Wth, bf16* __restrict__ Wtl,
    int K, int N)
{
    __shared__ float s[32][33];
    const int c0 = blockIdx.x * 32;
    const int r0 = blockIdx.y * 32;
    const int tx = threadIdx.x, ty = threadIdx.y;
    for (int i = ty; i < 32; i += 8)
        s[i][tx] = W[(size_t)(r0 + i) * N + c0 + tx];
    __syncthreads();
    for (int i = ty; i < 32; i += 8) {
        float v = s[tx][i];              // W[r0+tx][c0+i]
        bf16 h, l; bsplit(v, h, l);
        size_t o = (size_t)(c0 + i) * K + r0 + tx;
        Wth[o] = h; Wtl[o] = l;
    }
}

// V [4096][256] fp32 -> Vt [b*256 + c][t] bf16 hi/lo
__global__ __launch_bounds__(256) void vtrans_split(
    const float* __restrict__ V, bf16* __restrict__ Vth, bf16* __restrict__ Vtl)
{
    __shared__ float s[32][33];
    const int c0 = blockIdx.x * 32;      // 0..255
    const int r0 = blockIdx.y * 32;      // 0..4095
    const int b  = r0 >> 11;
    const int t0 = r0 & 2047;
    const int tx = threadIdx.x, ty = threadIdx.y;
    for (int i = ty; i < 32; i += 8)
        s[i][tx] = V[(size_t)(r0 + i) * KVW + c0 + tx];
    __syncthreads();
    for (int i = ty; i < 32; i += 8) {
        float v = s[tx][i];
        bf16 h, l; bsplit(v, h, l);
        size_t o = (size_t)(b * KVW + c0 + i) * TT + t0 + tx;
        Vth[o] = h; Vtl[o] = l;
    }
}

// x fp32 -> bf16 hi/lo (no transpose)
__global__ __launch_bounds__(256) void split_x(
    const float4* __restrict__ src, bf16* __restrict__ hi, bf16* __restrict__ lo, int n4)
{
    int i = blockIdx.x * 256 + threadIdx.x;
    if (i >= n4) return;
    float4 v = src[i];
    bf16 hx, lx, hy, ly, hz, lz, hw, lw;
    bsplit(v.x, hx, lx); bsplit(v.y, hy, ly);
    bsplit(v.z, hz, lz); bsplit(v.w, hw, lw);
    __nv_bfloat162 a, b2;
    a.x = hx; a.y = hy; b2.x = hz; b2.y = hw;
    ((__nv_bfloat162*)hi)[2 * i] = a; ((__nv_bfloat162*)hi)[2 * i + 1] = b2;
    a.x = lx; a.y = ly; b2.x = lz; b2.y = lw;
    ((__nv_bfloat162*)lo)[2 * i] = a; ((__nv_bfloat162*)lo)[2 * i + 1] = b2;
}

// ---------------- GEMM 3-pass bf16 ----------------
// C[M,N] = (Ah+Al) @ (Bh+Bl)^T + bias   (B given as Bt [N][K]; drops Al*Bl)
// Block 128x128, BK=16, 256 threads, warp tile 64x32.
__device__ __forceinline__ void gemm3p_body(
    const bf16* __restrict__ Ah, const bf16* __restrict__ Al,
    const bf16* __restrict__ Bth, const bf16* __restrict__ Btl,
    const float* __restrict__ bias, float* __restrict__ C,
    int M, int N, int K)
{
    __shared__ bf16 sAh[128][24], sAl[128][24], sBh[128][24], sBl[128][24];

    const int tid  = threadIdx.x;
    const int w    = tid >> 5, lane = tid & 31;
    const int lg   = lane >> 2, tg = lane & 3;
    const int m0   = (w & 1) * 64;
    const int n0   = (w >> 1) * 32;
    const int blkM = blockIdx.y * 128;
    const int blkN = blockIdx.x * 128;

    const int lrow = tid >> 1;
    const int lk   = (tid & 1) * 8;

    float acc[4][4][4];
#pragma unroll
    for (int i = 0; i < 4; i++)
#pragma unroll
        for (int j = 0; j < 4; j++)
#pragma unroll
            for (int v = 0; v < 4; v++) acc[i][j][v] = 0.f;

    const bf16* pAh = Ah  + (size_t)(blkM + lrow) * K + lk;
    const bf16* pAl = Al  + (size_t)(blkM + lrow) * K + lk;
    const bf16* pBh = Bth + (size_t)(blkN + lrow) * K + lk;
    const bf16* pBl = Btl + (size_t)(blkN + lrow) * K + lk;

    uint4 rAh = *(const uint4*)pAh;
    uint4 rAl = *(const uint4*)pAl;
    uint4 rBh = *(const uint4*)pBh;
    uint4 rBl = *(const uint4*)pBl;

    const int niter = K / 16;
    for (int it = 0; it < niter; it++) {
        *(uint4*)&sAh[lrow][lk] = rAh;
        *(uint4*)&sAl[lrow][lk] = rAl;
        *(uint4*)&sBh[lrow][lk] = rBh;
        *(uint4*)&sBl[lrow][lk] = rBl;
        __syncthreads();

        if (it + 1 < niter) {
            rAh = *(const uint4*)(pAh + (it + 1) * 16);
            rAl = *(const uint4*)(pAl + (it + 1) * 16);
            rBh = *(const uint4*)(pBh + (it + 1) * 16);
            rBl = *(const uint4*)(pBl + (it + 1) * 16);
        }

        uint32_t ah[4][4], al[4][4], bh[4][2], bl[4][2];
#pragma unroll
        for (int mt = 0; mt < 4; mt++) {
            const int r = m0 + mt * 16 + lg;
            ah[mt][0] = *(const uint32_t*)&sAh[r][tg * 2];
            ah[mt][1] = *(const uint32_t*)&sAh[r + 8][tg * 2];
            ah[mt][2] = *(const uint32_t*)&sAh[r][tg * 2 + 8];
            ah[mt][3] = *(const uint32_t*)&sAh[r + 8][tg * 2 + 8];
            al[mt][0] = *(const uint32_t*)&sAl[r][tg * 2];
            al[mt][1] = *(const uint32_t*)&sAl[r + 8][tg * 2];
            al[mt][2] = *(const uint32_t*)&sAl[r][tg * 2 + 8];
            al[mt][3] = *(const uint32_t*)&sAl[r + 8][tg * 2 + 8];
        }
#pragma unroll
        for (int nt = 0; nt < 4; nt++) {
            const int n = n0 + nt * 8 + lg;
            bh[nt][0] = *(const uint32_t*)&sBh[n][tg * 2];
            bh[nt][1] = *(const uint32_t*)&sBh[n][tg * 2 + 8];
            bl[nt][0] = *(const uint32_t*)&sBl[n][tg * 2];
            bl[nt][1] = *(const uint32_t*)&sBl[n][tg * 2 + 8];
        }
#pragma unroll
        for (int mt = 0; mt < 4; mt++)
#pragma unroll
            for (int nt = 0; nt < 4; nt++) {
                mma_bf16(acc[mt][nt], ah[mt][0], ah[mt][1], ah[mt][2], ah[mt][3],
                         bh[nt][0], bh[nt][1]);
                mma_bf16(acc[mt][nt], al[mt][0], al[mt][1], al[mt][2], al[mt][3],
                         bh[nt][0], bh[nt][1]);
                mma_bf16(acc[mt][nt], ah[mt][0], ah[mt][1], ah[mt][2], ah[mt][3],
                         bl[nt][0], bl[nt][1]);
            }
        __syncthreads();
    }

#pragma unroll
    for (int mt = 0; mt < 4; mt++)
#pragma unroll
        for (int nt = 0; nt < 4; nt++) {
            const int col = blkN + n0 + nt * 8 + 2 * tg;
            const float b0 = bias[col], b1 = bias[col + 1];
            const int r0 = blkM + m0 + mt * 16 + lg;
            float2 o;
            o.x = acc[mt][nt][0] + b0; o.y = acc[mt][nt][1] + b1;
            *(float2*)(C + (size_t)r0 * N + col) = o;
            o.x = acc[mt][nt][2] + b0; o.y = acc[mt][nt][3] + b1;
            *(float2*)(C + (size_t)(r0 + 8) * N + col) = o;
        }
}

__global__ __launch_bounds__(256) void gemm3p(
    const bf16* __restrict__ Ah, const bf16* __restrict__ Al,
    const bf16* __restrict__ Bth, const bf16* __restrict__ Btl,
    const float* __restrict__ bias, float* __restrict__ C,
    int M, int N, int K)
{
    gemm3p_body(Ah, Al, Bth, Btl, bias, C, M, N, K);
}

__global__ __launch_bounds__(256) void gemm3p_kv(
    const bf16* __restrict__ Ah, const bf16* __restrict__ Al,
    const bf16* __restrict__ Wkth, const bf16* __restrict__ Wktl,
    const float* __restrict__ bk, float* __restrict__ Kout,
    const bf16* __restrict__ Wvth, const bf16* __restrict__ Wvtl,
    const float* __restrict__ bv, float* __restrict__ Vout)
{
    if (blockIdx.z == 0) gemm3p_body(Ah, Al, Wkth, Wktl, bk, Kout, ROWS, KVW, EE);
    else                 gemm3p_body(Ah, Al, Wvth, Wvtl, bv, Vout, ROWS, KVW, EE);
}

// ---------------- RoPE + split ----------------
__global__ __launch_bounds__(256) void rope_split(
    const float* __restrict__ buf, bf16* __restrict__ hi,
    bf16* __restrict__ lo, int nheads)
{
    int idx = blockIdx.x * 256 + threadIdx.x;
    int ii  = idx & 31;
    int h   = (idx >> 5) % nheads;
    int row = idx / (32 * nheads);
    int t   = row & (TT - 1);
    float ang = (float)(t + 1) * exp2f((float)ii * (-13.2877123795494f / 32.0f));
    float sn, cs;
    sincosf(ang, &sn, &cs);
    size_t off = (size_t)row * (nheads * 64) + h * 64 + ii;
    float x0 = buf[off], x1 = buf[off + 32];
    float y0 = x0 * cs - x1 * sn;
    float y1 = x1 * cs + x0 * sn;
    bf16 h0, l0, h1, l1;
    bsplit(y0, h0, l0);
    bsplit(y1, h1, l1);
    hi[off] = h0; hi[off + 32] = h1;
    lo[off] = l0; lo[off + 32] = l1;
}

// ---------------- scores: S = QK^T / 8, 128x128 tiles ----------------
__global__ __launch_bounds__(256) void attn_scores_bf16(
    const bf16* __restrict__ Qh, const bf16* __restrict__ Ql,
    const bf16* __restrict__ Kh, const bf16* __restrict__ Kl,
    float* __restrict__ att)
{
    int idx = blockIdx.x;
    int qb = (int)((sqrtf(8.f * idx + 1.f) - 1.f) * 0.5f);
    while ((qb + 1) * (qb + 2) / 2 <= idx) qb++;
    while (qb * (qb + 1) / 2 > idx) qb--;
    const int kb = idx - qb * (qb + 1) / 2;

    const int z   = blockIdx.y;
    const int b   = z >> 4;
    const int g   = (z >> 2) & 3;
    const int hkv = z & 3;
    const int hq  = hkv * GG + g;

    extern __shared__ bf16 sm[];
    bf16 (*sQh)[72] = (bf16(*)[72])sm;
    bf16 (*sQl)[72] = (bf16(*)[72])(sm + 128 * 72);
    bf16 (*sKh)[72] = (bf16(*)[72])(sm + 2 * 128 * 72);
    bf16 (*sKl)[72] = (bf16(*)[72])(sm + 3 * 128 * 72);

    const int tid  = threadIdx.x;
    const int w    = tid >> 5, lane = tid & 31;
    const int lg   = lane >> 2, tg = lane & 3;
    const int m0   = (w & 1) * 64;
    const int n0   = (w >> 1) * 32;

    {
        const int lrow = tid >> 1;
        const int lc   = (tid & 1) * 32;
        const bf16* qh = Qh + (size_t)(b * TT + qb * 128 + lrow) * EE + hq * 64 + lc;
        const bf16* ql = Ql + (size_t)(b * TT + qb * 128 + lrow) * EE + hq * 64 + lc;
        const bf16* kh = Kh + (size_t)(b * TT + kb * 128 + lrow) * KVW + hkv * 64 + lc;
        const bf16* kl = Kl + (size_t)(b * TT + kb * 128 + lrow) * KVW + hkv * 64 + lc;
#pragma unroll
        for (int v = 0; v < 4; v++) {
            *(uint4*)&sQh[lrow][lc + v * 8] = *(const uint4*)(qh + v * 8);
            *(uint4*)&sQl[lrow][lc + v * 8] = *(const uint4*)(ql + v * 8);
            *(uint4*)&sKh[lrow][lc + v * 8] = *(const uint4*)(kh + v * 8);
            *(uint4*)&sKl[lrow][lc + v * 8] = *(const uint4*)(kl + v * 8);
        }
    }
    __syncthreads();

    float acc[4][4][4];
#pragma unroll
    for (int i = 0; i < 4; i++)
#pragma unroll
        for (int j = 0; j < 4; j++)
#pragma unroll
            for (int v = 0; v < 4; v++) acc[i][j][v] = 0.f;

#pragma unroll
    for (int kk = 0; kk < 64; kk += 16) {
        uint32_t ah[4][4], al[4][4], bh[4][2], bl[4][2];
#pragma unroll
        for (int mt = 0; mt < 4; mt++) {
            const int r = m0 + mt * 16 + lg;
            ah[mt][0] = *(const uint32_t*)&sQh[r][kk + tg * 2];
            ah[mt][1] = *(const uint32_t*)&sQh[r + 8][kk + tg * 2];
            ah[mt][2] = *(const uint32_t*)&sQh[r][kk + tg * 2 + 8];
            ah[mt][3] = *(const uint32_t*)&sQh[r + 8][kk + tg * 2 + 8];
            al[mt][0] = *(const uint32_t*)&sQl[r][kk + tg * 2];
            al[mt][1] = *(const uint32_t*)&sQl[r + 8][kk + tg * 2];
            al[mt][2] = *(const uint32_t*)&sQl[r][kk + tg * 2 + 8];
            al[mt][3] = *(const uint32_t*)&sQl[r + 8][kk + tg * 2 + 8];
        }
#pragma unroll
        for (int nt = 0; nt < 4; nt++) {
            const int n = n0 + nt * 8 + lg;
            bh[nt][0] = *(const uint32_t*)&sKh[n][kk + tg * 2];
            bh[nt][1] = *(const uint32_t*)&sKh[n][kk + tg * 2 + 8];
            bl[nt][0] = *(const uint32_t*)&sKl[n][kk + tg * 2];
            bl[nt][1] = *(const uint32_t*)&sKl[n][kk + tg * 2 + 8];
        }
#pragma unroll
        for (int mt = 0; mt < 4; mt++)
#pragma unroll
            for (int nt = 0; nt < 4; nt++) {
                mma_bf16(acc[mt][nt], ah[mt][0], ah[mt][1], ah[mt][2], ah[mt][3],
                         bh[nt][0], bh[nt][1]);
                mma_bf16(acc[mt][nt], al[mt][0], al[mt][1], al[mt][2], al[mt][3],
                         bh[nt][0], bh[nt][1]);
                mma_bf16(acc[mt][nt], ah[mt][0], ah[mt][1], ah[mt][2], ah[mt][3],
                         bl[nt][0], bl[nt][1]);
            }
    }

    float* obase = att + ((size_t)z * TT + qb * 128) * TT + kb * 128;
#pragma unroll
    for (int mt = 0; mt < 4; mt++)
#pragma unroll
        for (int nt = 0; nt < 4; nt++) {
            const int col = n0 + nt * 8 + 2 * tg;
            const int r0 = m0 + mt * 16 + lg;
            float2 o;
            o.x = acc[mt][nt][0] * 0.125f; o.y = acc[mt][nt][1] * 0.125f;
            *(float2*)(obase + (size_t)r0 * TT + col) = o;
            o.x = acc[mt][nt][2] * 0.125f; o.y = acc[mt][nt][3] * 0.125f;
            *(float2*)(obase + (size_t)(r0 + 8) * TT + col) = o;
        }
}

// ---------------- softmax ----------------
__device__ __forceinline__ float warpReduceMax(float v)
{
#pragma unroll
    for (int o = 16; o > 0; o >>= 1) v = fmaxf(v, __shfl_xor_sync(0xffffffffu, v, o));
    return v;
}
__device__ __forceinline__ float warpReduceSum(float v)
{
#pragma unroll
    for (int o = 16; o > 0; o >>= 1) v += __shfl_xor_sync(0xffffffffu, v, o);
    return v;
}

__global__ __launch_bounds__(256) void softmax_reg(float* __restrict__ att)
{
    const int q = blockIdx.x;
    const int z = blockIdx.y;
    float* row = att + ((size_t)z * TT + q) * TT;
    const int n = q + 1;
    const int tid = threadIdx.x;
    __shared__ float red[8];

    float r[8];
    float m = -1e30f;
#pragma unroll
    for (int it = 0; it < 8; it++) {
        int idx = tid + it * 256;
        r[it] = (idx < n) ? row[idx] : -1e30f;
        m = fmaxf(m, r[it]);
    }
    m = warpReduceMax(m);
    if ((tid & 31) == 0) red[tid >> 5] = m;
    __syncthreads();
    {
        float v = (tid < 8) ? red[tid] : -1e30f;
        v = warpReduceMax(v);
        if (tid == 0) red[0] = v;
    }
    __syncthreads();
    const float M = red[0];
    __syncthreads();

    float s = 0.f;
#pragma unroll
    for (int it = 0; it < 8; it++) {
        int idx = tid + it * 256;
        float e = (idx < n) ? __expf(r[it] - M) : 0.f;
        r[it] = e;
        s += e;
    }
    s = warpReduceSum(s);
    if ((tid & 31) == 0) red[tid >> 5] = s;
    __syncthreads();
    {
        float v = (tid < 8) ? red[tid] : 0.f;
        v = warpReduceSum(v);
        if (tid == 0) red[0] = v;
    }
    __syncthreads();
    const float inv = 1.0f / red[0];

#pragma unroll
    for (int it = 0; it < 8; it++) {
        int idx = tid + it * 256;
        row[idx] = r[it] * inv;
    }
}

// ---------------- PV: Y = P @ V, 128q x 64d tiles ----------------
__global__ __launch_bounds__(256) void attn_pv_bf16(
    const float* __restrict__ att, const bf16* __restrict__ Vth,
    const bf16* __restrict__ Vtl, bf16* __restrict__ Yh, bf16* __restrict__ Yl)
{
    const int qb = (gridDim.x - 1) - blockIdx.x;   // heavy blocks first
    const int z  = blockIdx.y;
    const int b   = z >> 4;
    const int g   = (z >> 2) & 3;
    const int hkv = z & 3;

    extern __shared__ bf16 sm[];
    bf16 (*sPh)[72] = (bf16(*)[72])sm;
    bf16 (*sPl)[72] = (bf16(*)[72])(sm + 128 * 72);
    bf16 (*sVh)[72] = (bf16(*)[72])(sm + 2 * 128 * 72);
    bf16 (*sVl)[72] = (bf16(*)[72])(sm + 2 * 128 * 72 + 64 * 72);

    const int tid  = threadIdx.x;
    const int w    = tid >> 5, lane = tid & 31;
    const int lg   = lane >> 2, tg = lane & 3;
    const int m0   = (w & 3) * 32;
    const int n0   = (w >> 2) * 32;

    const int prow = tid >> 1;
    const int pc   = (tid & 1) * 32;
    const int vrow = tid >> 2;
    const int vc   = (tid & 3) * 16;

    float acc[2][4][4];
#pragma unroll
    for (int i = 0; i < 2; i++)
#pragma unroll
        for (int j = 0; j < 4; j++)
#pragma unroll
            for (int v = 0; v < 4; v++) acc[i][j][v] = 0.f;

    const float* attrow = att + ((size_t)z * TT + qb * 128 + prow) * TT + pc;
    const bf16* vbh = Vth + (size_t)(b * KVW + hkv * 64 + vrow) * TT + vc;
    const bf16* vbl = Vtl + (size_t)(b * KVW + hkv * 64 + vrow) * TT + vc;

    const int nkb = 2 * qb + 2;
    for (int kb = 0; kb < nkb; kb++) {
#pragma unroll
        for (int v = 0; v < 8; v++) {
            float4 p = *(const float4*)(attrow + kb * 64 + v * 4);
            bf16 h0, l0, h1, l1, h2, l2, h3, l3;
            bsplit(p.x, h0, l0); bsplit(p.y, h1, l1);
            bsplit(p.z, h2, l2); bsplit(p.w, h3, l3);
            __nv_bfloat162 t;
            t.x = h0; t.y = h1; *(__nv_bfloat162*)&sPh[prow][pc + v * 4] = t;
            t.x = h2; t.y = h3; *(__nv_bfloat162*)&sPh[prow][pc + v * 4 + 2] = t;
            t.x = l0; t.y = l1; *(__nv_bfloat162*)&sPl[prow][pc + v * 4] = t;
            t.x = l2; t.y = l3; *(__nv_bfloat162*)&sPl[prow][pc + v * 4 + 2] = t;
        }
        *(uint4*)&sVh[vrow][vc]     = *(const uint4*)(vbh + kb * 64);
        *(uint4*)&sVh[vrow][vc + 8] = *(const uint4*)(vbh + kb * 64 + 8);
        *(uint4*)&sVl[vrow][vc]     = *(const uint4*)(vbl + kb * 64);
        *(uint4*)&sVl[vrow][vc + 8] = *(const uint4*)(vbl + kb * 64 + 8);
        __syncthreads();

#pragma unroll
        for (int kk = 0; kk < 64; kk += 16) {
            uint32_t ah[2][4], al[2][4], bh[4][2], bl[4][2];
#pragma unroll
            for (int mt = 0; mt < 2; mt++) {
                const int r = m0 + mt * 16 + lg;
                ah[mt][0] = *(const uint32_t*)&sPh[r][kk + tg * 2];
                ah[mt][1] = *(const uint32_t*)&sPh[r + 8][kk + tg * 2];
                ah[mt][2] = *(const uint32_t*)&sPh[r][kk + tg * 2 + 8];
                ah[mt][3] = *(const uint32_t*)&sPh[r + 8][kk + tg * 2 + 8];
                al[mt][0] = *(const uint32_t*)&sPl[r][kk + tg * 2];
                al[mt][1] = *(const uint32_t*)&sPl[r + 8][kk + tg * 2];
                al[mt][2] = *(const uint32_t*)&sPl[r][kk + tg * 2 + 8];
                al[mt][3] = *(const uint32_t*)&sPl[r + 8][kk + tg * 2 + 8];
            }
#pragma unroll
            for (int nt = 0; nt < 4; nt++) {
                const int n = n0 + nt * 8 + lg;
                bh[nt][0] = *(const uint32_t*)&sVh[n][kk + tg * 2];
                bh[nt][1] = *(const uint32_t*)&sVh[n][kk + tg * 2 + 8];
                bl[nt][0] = *(const uint32_t*)&sVl[n][kk + tg * 2];
                bl[nt][1] = *(const uint32_t*)&sVl[n][kk + tg * 2 + 8];
            }
#pragma unroll
            for (int mt = 0; mt < 2; mt++)
#pragma unroll
                for (int nt = 0; nt < 4; nt++) {
                    mma_bf16(acc[mt][nt], ah[mt][0], ah[mt][1], ah[mt][2], ah[mt][3],
                             bh[nt][0], bh[nt][1]);
                    mma_bf16(acc[mt][nt], al[mt][0], al[mt][1], al[mt][2], al[mt][3],
                             bh[nt][0], bh[nt][1]);
                    mma_bf16(acc[mt][nt], ah[mt][0], ah[mt][1], ah[mt][2], ah[mt][3],
                             bl[nt][0], bl[nt][1]);
                }
        }
        __syncthreads();
    }

    const int colbase = hkv * 256 + g * 64;
#pragma unroll
    for (int mt = 0; mt < 2; mt++)
#pragma unroll
        for (int nt = 0; nt < 4; nt++) {
            const int col = colbase + n0 + nt * 8 + 2 * tg;
            const int r0 = b * TT + qb * 128 + m0 + mt * 16 + lg;
            bf16 h0, l0, h1, l1;
            __nv_bfloat162 t;
            bsplit(acc[mt][nt][0], h0, l0); bsplit(acc[mt][nt][1], h1, l1);
            t.x = h0; t.y = h1; *(__nv_bfloat162*)&Yh[(size_t)r0 * EE + col] = t;
            t.x = l0; t.y = l1; *(__nv_bfloat162*)&Yl[(size_t)r0 * EE + col] = t;
            bsplit(acc[mt][nt][2], h0, l0); bsplit(acc[mt][nt][3], h1, l1);
            t.x = h0; t.y = h1; *(__nv_bfloat162*)&Yh[(size_t)(r0 + 8) * EE + col] = t;
            t.x = l0; t.y = l1; *(__nv_bfloat162*)&Yl[(size_t)(r0 + 8) * EE + col] = t;
        }
}

// ---------------- launch ----------------
extern "C" void kernel_launch(void* const* d_in, const int* in_sizes, int n_in,
                              void* d_out, int out_size)
{
    const float* x  = (const float*)d_in[0];
    const float* Wq = (const float*)d_in[2];
    const float* bq = (const float*)d_in[3];
    const float* Wk = (const float*)d_in[4];
    const float* bk = (const float*)d_in[5];
    const float* Wv = (const float*)d_in[6];
    const float* bv = (const float*)d_in[7];
    const float* Wo = (const float*)d_in[8];
    const float* bo = (const float*)d_in[9];
    float* out = (float*)d_out;

    float *Qb, *Kb, *Vb, *attScratch;
    bf16 *xh, *xl, *Qh, *Ql, *Kh, *Kl, *Vth, *Vtl, *Yh, *Yl;
    bf16 *Wqth, *Wqtl, *Wkth, *Wktl, *Wvth, *Wvtl, *Woth, *Wotl;
    cudaGetSymbolAddress((void**)&Qb, g_Q);
    cudaGetSymbolAddress((void**)&Kb, g_K);
    cudaGetSymbolAddress((void**)&Vb, g_V);
    cudaGetSymbolAddress((void**)&attScratch, g_Att);
    cudaGetSymbolAddress((void**)&xh, g_xh);
    cudaGetSymbolAddress((void**)&xl, g_xl);
    cudaGetSymbolAddress((void**)&Qh, g_Qh);
    cudaGetSymbolAddress((void**)&Ql, g_Ql);
    cudaGetSymbolAddress((void**)&Kh, g_Kh);
    cudaGetSymbolAddress((void**)&Kl, g_Kl);
    cudaGetSymbolAddress((void**)&Vth, g_Vth);
    cudaGetSymbolAddress((void**)&Vtl, g_Vtl);
    cudaGetSymbolAddress((void**)&Yh, g_Yh);
    cudaGetSymbolAddress((void**)&Yl, g_Yl);
    cudaGetSymbolAddress((void**)&Wqth, g_Wqth);
    cudaGetSymbolAddress((void**)&Wqtl, g_Wqtl);
    cudaGetSymbolAddress((void**)&Wkth, g_Wkth);
    cudaGetSymbolAddress((void**)&Wktl, g_Wktl);
    cudaGetSymbolAddress((void**)&Wvth, g_Wvth);
    cudaGetSymbolAddress((void**)&Wvtl, g_Wvtl);
    cudaGetSymbolAddress((void**)&Woth, g_Woth);
    cudaGetSymbolAddress((void**)&Wotl, g_Wotl);

    float* att = ((size_t)out_size >= Y_ELEMS + ATT_ELEMS) ? (out + Y_ELEMS)
                                                           : attScratch;

    const int SMEM_SC = 4 * 128 * 72 * (int)sizeof(bf16);            // 73728
    const int SMEM_PV = (2 * 128 + 2 * 64) * 72 * (int)sizeof(bf16); // 55296
    cudaFuncSetAttribute(attn_scores_bf16, cudaFuncAttributeMaxDynamicSharedMemorySize, SMEM_SC);
    cudaFuncSetAttribute(attn_pv_bf16,    cudaFuncAttributeMaxDynamicSharedMemorySize, SMEM_PV);

    // 0) weight transpose+split, x split
    wtrans_split<<<dim3(EE / 32, EE / 32),  dim3(32, 8)>>>(Wq, Wqth, Wqtl, EE, EE);
    wtrans_split<<<dim3(KVW / 32, EE / 32), dim3(32, 8)>>>(Wk, Wkth, Wktl, EE, KVW);
    wtrans_split<<<dim3(KVW / 32, EE / 32), dim3(32, 8)>>>(Wv, Wvth, Wvtl, EE, KVW);
    wtrans_split<<<dim3(EE / 32, EE / 32),  dim3(32, 8)>>>(Wo, Woth, Wotl, EE, EE);
    split_x<<<(ROWS * EE / 4 + 255) / 256, 256>>>((const float4*)x, xh, xl, ROWS * EE / 4);

    // 1) projections
    gemm3p<<<dim3(EE / 128, ROWS / 128), 256>>>(xh, xl, Wqth, Wqtl, bq, Qb, ROWS, EE, EE);
    gemm3p_kv<<<dim3(KVW / 128, ROWS / 128, 2), 256>>>(xh, xl, Wkth, Wktl, bk, Kb,
                                                       Wvth, Wvtl, bv, Vb);

    // 2) RoPE + split; V transpose+split
    rope_split<<<(ROWS * HQn * 32) / 256, 256>>>(Qb, Qh, Ql, HQn);
    rope_split<<<(ROWS * HKVn * 32) / 256, 256>>>(Kb, Kh, Kl, HKVn);
    vtrans_split<<<dim3(KVW / 32, ROWS / 32), dim3(32, 8)>>>(Vb, Vth, Vtl);

    // 3) scores (triangular grid, 128x128 tiles)
    attn_scores_bf16<<<dim3(16 * 17 / 2, BB * HQn), 256, SMEM_SC>>>(Qh, Ql, Kh, Kl, att);

    // 4) softmax
    softmax_reg<<<dim3(TT, BB * HQn), 256>>>(att);

    // 5) PV -> Yh/Yl (bf16, permuted layout)
    attn_pv_bf16<<<dim3(TT / 128, BB * HQn), 256, SMEM_PV>>>(att, Vth, Vtl, Yh, Yl);

    // 6) output projection
    gemm3p<<<dim3(EE / 128, ROWS / 128), 256>>>(Yh, Yl, Woth, Wotl, bo, out, ROWS, EE, EE);
}

// round 5
// speedup vs baseline: 2.3939x; 1.2019x over previous
#include <cuda_runtime.h>
#include <cuda_fp16.h>
#include <math.h>
#include <stdint.h>

#define BB   2
#define TT   2048
#define EE   1024
#define HQn  16
#define HKVn 4
#define DD   64
#define GG   4

#define ROWS (BB*TT)
#define KVW  (HKVn*DD)
#define Y_ELEMS  ((size_t)BB*TT*EE)
#define ATT_ELEMS ((size_t)BB*HQn*TT*TT)

typedef __half h16;

// ---------------- device scratch ----------------
__device__ float g_Q[ROWS * EE];
__device__ float g_K[ROWS * KVW];
__device__ float g_V[ROWS * KVW];
__device__ float g_Att[ATT_ELEMS];

__device__ h16 g_xh[ROWS * EE],  g_xl[ROWS * EE];
__device__ h16 g_Qh[ROWS * EE],  g_Ql[ROWS * EE];
__device__ h16 g_Kh[ROWS * KVW], g_Kl[ROWS * KVW];   // Kl written, unused (cheap)
__device__ h16 g_Vth[BB * KVW * TT];                 // [(b*4+hkv)*64+d][t]
__device__ h16 g_Yh[ROWS * EE],  g_Yl[ROWS * EE];
__device__ h16 g_Wqth[EE * EE];                      // [N][K], hi only
__device__ h16 g_Wkth[EE * KVW];
__device__ h16 g_Wvth[EE * KVW];
__device__ h16 g_Woth[EE * EE];

// ---------------- helpers ----------------
__device__ __forceinline__ void hsplit(float x, h16& h, h16& l)
{
    h = __float2half_rn(x);
    l = __float2half_rn(x - __half2float(h));
}

__device__ __forceinline__ void mma_f16(float (&c)[4],
                                        uint32_t a0, uint32_t a1,
                                        uint32_t a2, uint32_t a3,
                                        uint32_t b0, uint32_t b1)
{
    asm volatile(
        "mma.sync.aligned.m16n8k16.row.col.f32.f16.f16.f32 "
        "{%0,%1,%2,%3}, {%4,%5,%6,%7}, {%8,%9}, {%0,%1,%2,%3};"
        : "+f"(c[0]), "+f"(c[1]), "+f"(c[2]), "+f"(c[3])
        : "r"(a0), "r"(a1), "r"(a2), "r"(a3), "r"(b0), "r"(b1));
}

// ---------------- preprocessing ----------------
// W [K][N] fp32 -> Wt [N][K] fp16 (hi only)
__global__ __launch_bounds__(256) void wtrans_half(
    const float* __restrict__ W, h16* __restrict__ Wth, int K, int N)
{
    __shared__ float s[32][33];
    const int c0 = blockIdx.x * 32;
    const int r0 = blockIdx.y * 32;
    const int tx = threadIdx.x, ty = threadIdx.y;
    for (int i = ty; i < 32; i += 8)
        s[i][tx] = W[(size_t)(r0 + i) * N + c0 + tx];
    __syncthreads();
    for (int i = ty; i < 32; i += 8)
        Wth[(size_t)(c0 + i) * K + r0 + tx] = __float2half_rn(s[tx][i]);
}

// V [4096][256] fp32 -> Vt [(b*256+c)][t] fp16 hi
__global__ __launch_bounds__(256) void vtrans_half(
    const float* __restrict__ V, h16* __restrict__ Vth)
{
    __shared__ float s[32][33];
    const int c0 = blockIdx.x * 32;
    const int r0 = blockIdx.y * 32;
    const int b  = r0 >> 11;
    const int t0 = r0 & 2047;
    const int tx = threadIdx.x, ty = threadIdx.y;
    for (int i = ty; i < 32; i += 8)
        s[i][tx] = V[(size_t)(r0 + i) * KVW + c0 + tx];
    __syncthreads();
    for (int i = ty; i < 32; i += 8)
        Vth[(size_t)(b * KVW + c0 + i) * TT + t0 + tx] = __float2half_rn(s[tx][i]);
}

// x fp32 -> fp16 hi/lo
__global__ __launch_bounds__(256) void split_x(
    const float4* __restrict__ src, h16* __restrict__ hi, h16* __restrict__ lo, int n4)
{
    int i = blockIdx.x * 256 + threadIdx.x;
    if (i >= n4) return;
    float4 v = src[i];
    h16 hx, lx, hy, ly, hz, lz, hw, lw;
    hsplit(v.x, hx, lx); hsplit(v.y, hy, ly);
    hsplit(v.z, hz, lz); hsplit(v.w, hw, lw);
    __half2 a, b2;
    a.x = hx; a.y = hy; b2.x = hz; b2.y = hw;
    ((__half2*)hi)[2 * i] = a; ((__half2*)hi)[2 * i + 1] = b2;
    a.x = lx; a.y = ly; b2.x = lz; b2.y = lw;
    ((__half2*)lo)[2 * i] = a; ((__half2*)lo)[2 * i + 1] = b2;
}

// ---------------- GEMM 2-pass fp16 ----------------
// C[M,N] = (Ah+Al) @ Bh^T + bias   (Bt [N][K], drops a*bl)
__device__ __forceinline__ void gemm2p_body(
    const h16* __restrict__ Ah, const h16* __restrict__ Al,
    const h16* __restrict__ Bth, const float* __restrict__ bias,
    float* __restrict__ C, int M, int N, int K)
{
    __shared__ h16 sAh[128][24], sAl[128][24], sBh[128][24];

    const int tid  = threadIdx.x;
    const int w    = tid >> 5, lane = tid & 31;
    const int lg   = lane >> 2, tg = lane & 3;
    const int m0   = (w & 1) * 64;
    const int n0   = (w >> 1) * 32;
    const int blkM = blockIdx.y * 128;
    const int blkN = blockIdx.x * 128;

    const int lrow = tid >> 1;
    const int lk   = (tid & 1) * 8;

    float acc[4][4][4];
#pragma unroll
    for (int i = 0; i < 4; i++)
#pragma unroll
        for (int j = 0; j < 4; j++)
#pragma unroll
            for (int v = 0; v < 4; v++) acc[i][j][v] = 0.f;

    const h16* pAh = Ah  + (size_t)(blkM + lrow) * K + lk;
    const h16* pAl = Al  + (size_t)(blkM + lrow) * K + lk;
    const h16* pBh = Bth + (size_t)(blkN + lrow) * K + lk;

    uint4 rAh = *(const uint4*)pAh;
    uint4 rAl = *(const uint4*)pAl;
    uint4 rBh = *(const uint4*)pBh;

    const int niter = K / 16;
    for (int it = 0; it < niter; it++) {
        *(uint4*)&sAh[lrow][lk] = rAh;
        *(uint4*)&sAl[lrow][lk] = rAl;
        *(uint4*)&sBh[lrow][lk] = rBh;
        __syncthreads();

        if (it + 1 < niter) {
            rAh = *(const uint4*)(pAh + (it + 1) * 16);
            rAl = *(const uint4*)(pAl + (it + 1) * 16);
            rBh = *(const uint4*)(pBh + (it + 1) * 16);
        }

        uint32_t ah[4][4], al[4][4], bh[4][2];
#pragma unroll
        for (int mt = 0; mt < 4; mt++) {
            const int r = m0 + mt * 16 + lg;
            ah[mt][0] = *(const uint32_t*)&sAh[r][tg * 2];
            ah[mt][1] = *(const uint32_t*)&sAh[r + 8][tg * 2];
            ah[mt][2] = *(const uint32_t*)&sAh[r][tg * 2 + 8];
            ah[mt][3] = *(const uint32_t*)&sAh[r + 8][tg * 2 + 8];
            al[mt][0] = *(const uint32_t*)&sAl[r][tg * 2];
            al[mt][1] = *(const uint32_t*)&sAl[r + 8][tg * 2];
            al[mt][2] = *(const uint32_t*)&sAl[r][tg * 2 + 8];
            al[mt][3] = *(const uint32_t*)&sAl[r + 8][tg * 2 + 8];
        }
#pragma unroll
        for (int nt = 0; nt < 4; nt++) {
            const int n = n0 + nt * 8 + lg;
            bh[nt][0] = *(const uint32_t*)&sBh[n][tg * 2];
            bh[nt][1] = *(const uint32_t*)&sBh[n][tg * 2 + 8];
        }
#pragma unroll
        for (int mt = 0; mt < 4; mt++)
#pragma unroll
            for (int nt = 0; nt < 4; nt++) {
                mma_f16(acc[mt][nt], ah[mt][0], ah[mt][1], ah[mt][2], ah[mt][3],
                        bh[nt][0], bh[nt][1]);
                mma_f16(acc[mt][nt], al[mt][0], al[mt][1], al[mt][2], al[mt][3],
                        bh[nt][0], bh[nt][1]);
            }
        __syncthreads();
    }

#pragma unroll
    for (int mt = 0; mt < 4; mt++)
#pragma unroll
        for (int nt = 0; nt < 4; nt++) {
            const int col = blkN + n0 + nt * 8 + 2 * tg;
            const float b0 = bias[col], b1 = bias[col + 1];
            const int r0 = blkM + m0 + mt * 16 + lg;
            float2 o;
            o.x = acc[mt][nt][0] + b0; o.y = acc[mt][nt][1] + b1;
            *(float2*)(C + (size_t)r0 * N + col) = o;
            o.x = acc[mt][nt][2] + b0; o.y = acc[mt][nt][3] + b1;
            *(float2*)(C + (size_t)(r0 + 8) * N + col) = o;
        }
}

__global__ __launch_bounds__(256) void gemm2p(
    const h16* __restrict__ Ah, const h16* __restrict__ Al,
    const h16* __restrict__ Bth, const float* __restrict__ bias,
    float* __restrict__ C, int M, int N, int K)
{
    gemm2p_body(Ah, Al, Bth, bias, C, M, N, K);
}

__global__ __launch_bounds__(256) void gemm2p_kv(
    const h16* __restrict__ Ah, const h16* __restrict__ Al,
    const h16* __restrict__ Wkth, const float* __restrict__ bk, float* __restrict__ Kout,
    const h16* __restrict__ Wvth, const float* __restrict__ bv, float* __restrict__ Vout)
{
    if (blockIdx.z == 0) gemm2p_body(Ah, Al, Wkth, bk, Kout, ROWS, KVW, EE);
    else                 gemm2p_body(Ah, Al, Wvth, bv, Vout, ROWS, KVW, EE);
}

// ---------------- RoPE + split ----------------
__global__ __launch_bounds__(256) void rope_split(
    const float* __restrict__ buf, h16* __restrict__ hi,
    h16* __restrict__ lo, int nheads)
{
    int idx = blockIdx.x * 256 + threadIdx.x;
    int ii  = idx & 31;
    int h   = (idx >> 5) % nheads;
    int row = idx / (32 * nheads);
    int t   = row & (TT - 1);
    float ang = (float)(t + 1) * exp2f((float)ii * (-13.2877123795494f / 32.0f));
    float sn, cs;
    sincosf(ang, &sn, &cs);
    size_t off = (size_t)row * (nheads * 64) + h * 64 + ii;
    float x0 = buf[off], x1 = buf[off + 32];
    float y0 = x0 * cs - x1 * sn;
    float y1 = x1 * cs + x0 * sn;
    h16 h0, l0, h1, l1;
    hsplit(y0, h0, l0);
    hsplit(y1, h1, l1);
    hi[off] = h0; hi[off + 32] = h1;
    lo[off] = l0; lo[off + 32] = l1;
}

// ---------------- scores: S = QK^T / 8, 128x128 tiles ----------------
__global__ __launch_bounds__(256) void attn_scores_f16(
    const h16* __restrict__ Qh, const h16* __restrict__ Ql,
    const h16* __restrict__ Kh, float* __restrict__ att)
{
    int idx = blockIdx.x;
    int qb = (int)((sqrtf(8.f * idx + 1.f) - 1.f) * 0.5f);
    while ((qb + 1) * (qb + 2) / 2 <= idx) qb++;
    while (qb * (qb + 1) / 2 > idx) qb--;
    const int kb = idx - qb * (qb + 1) / 2;

    const int z   = blockIdx.y;
    const int b   = z >> 4;
    const int g   = (z >> 2) & 3;
    const int hkv = z & 3;
    const int hq  = hkv * GG + g;

    extern __shared__ h16 sm[];
    h16 (*sQh)[72] = (h16(*)[72])sm;
    h16 (*sQl)[72] = (h16(*)[72])(sm + 128 * 72);
    h16 (*sKh)[72] = (h16(*)[72])(sm + 2 * 128 * 72);

    const int tid  = threadIdx.x;
    const int w    = tid >> 5, lane = tid & 31;
    const int lg   = lane >> 2, tg = lane & 3;
    const int m0   = (w & 1) * 64;
    const int n0   = (w >> 1) * 32;

    {
        const int lrow = tid >> 1;
        const int lc   = (tid & 1) * 32;
        const h16* qh = Qh + (size_t)(b * TT + qb * 128 + lrow) * EE + hq * 64 + lc;
        const h16* ql = Ql + (size_t)(b * TT + qb * 128 + lrow) * EE + hq * 64 + lc;
        const h16* kh = Kh + (size_t)(b * TT + kb * 128 + lrow) * KVW + hkv * 64 + lc;
#pragma unroll
        for (int v = 0; v < 4; v++) {
            *(uint4*)&sQh[lrow][lc + v * 8] = *(const uint4*)(qh + v * 8);
            *(uint4*)&sQl[lrow][lc + v * 8] = *(const uint4*)(ql + v * 8);
            *(uint4*)&sKh[lrow][lc + v * 8] = *(const uint4*)(kh + v * 8);
        }
    }
    __syncthreads();

    float acc[4][4][4];
#pragma unroll
    for (int i = 0; i < 4; i++)
#pragma unroll
        for (int j = 0; j < 4; j++)
#pragma unroll
            for (int v = 0; v < 4; v++) acc[i][j][v] = 0.f;

#pragma unroll
    for (int kk = 0; kk < 64; kk += 16) {
        uint32_t ah[4][4], al[4][4], bh[4][2];
#pragma unroll
        for (int mt = 0; mt < 4; mt++) {
            const int r = m0 + mt * 16 + lg;
            ah[mt][0] = *(const uint32_t*)&sQh[r][kk + tg * 2];
            ah[mt][1] = *(const uint32_t*)&sQh[r + 8][kk + tg * 2];
            ah[mt][2] = *(const uint32_t*)&sQh[r][kk + tg * 2 + 8];
            ah[mt][3] = *(const uint32_t*)&sQh[r + 8][kk + tg * 2 + 8];
            al[mt][0] = *(const uint32_t*)&sQl[r][kk + tg * 2];
            al[mt][1] = *(const uint32_t*)&sQl[r + 8][kk + tg * 2];
            al[mt][2] = *(const uint32_t*)&sQl[r][kk + tg * 2 + 8];
            al[mt][3] = *(const uint32_t*)&sQl[r + 8][kk + tg * 2 + 8];
        }
#pragma unroll
        for (int nt = 0; nt < 4; nt++) {
            const int n = n0 + nt * 8 + lg;
            bh[nt][0] = *(const uint32_t*)&sKh[n][kk + tg * 2];
            bh[nt][1] = *(const uint32_t*)&sKh[n][kk + tg * 2 + 8];
        }
#pragma unroll
        for (int mt = 0; mt < 4; mt++)
#pragma unroll
            for (int nt = 0; nt < 4; nt++) {
                mma_f16(acc[mt][nt], ah[mt][0], ah[mt][1], ah[mt][2], ah[mt][3],
                        bh[nt][0], bh[nt][1]);
                mma_f16(acc[mt][nt], al[mt][0], al[mt][1], al[mt][2], al[mt][3],
                        bh[nt][0], bh[nt][1]);
            }
    }

    float* obase = att + ((size_t)z * TT + qb * 128) * TT + kb * 128;
#pragma unroll
    for (int mt = 0; mt < 4; mt++)
#pragma unroll
        for (int nt = 0; nt < 4; nt++) {
            const int col = n0 + nt * 8 + 2 * tg;
            const int r0 = m0 + mt * 16 + lg;
            float2 o;
            o.x = acc[mt][nt][0] * 0.125f; o.y = acc[mt][nt][1] * 0.125f;
            *(float2*)(obase + (size_t)r0 * TT + col) = o;
            o.x = acc[mt][nt][2] * 0.125f; o.y = acc[mt][nt][3] * 0.125f;
            *(float2*)(obase + (size_t)(r0 + 8) * TT + col) = o;
        }
}

// ---------------- softmax (vectorized float4) ----------------
__device__ __forceinline__ float warpReduceMax(float v)
{
#pragma unroll
    for (int o = 16; o > 0; o >>= 1) v = fmaxf(v, __shfl_xor_sync(0xffffffffu, v, o));
    return v;
}
__device__ __forceinline__ float warpReduceSum(float v)
{
#pragma unroll
    for (int o = 16; o > 0; o >>= 1) v += __shfl_xor_sync(0xffffffffu, v, o);
    return v;
}

__global__ __launch_bounds__(256) void softmax_vec(float* __restrict__ att)
{
    const int q = blockIdx.x;
    const int z = blockIdx.y;
    float* row = att + ((size_t)z * TT + q) * TT;
    const int n = q + 1;
    const int tid = threadIdx.x;
    const int base = tid * 8;
    __shared__ float red[8];

    float4 a = *(float4*)(row + base);
    float4 b2 = *(float4*)(row + base + 4);
    float r[8] = {a.x, a.y, a.z, a.w, b2.x, b2.y, b2.z, b2.w};

    float m = -1e30f;
#pragma unroll
    for (int j = 0; j < 8; j++) {
        if (base + j >= n) r[j] = -1e30f;
        m = fmaxf(m, r[j]);
    }
    m = warpReduceMax(m);
    if ((tid & 31) == 0) red[tid >> 5] = m;
    __syncthreads();
    {
        float v = (tid < 8) ? red[tid] : -1e30f;
        v = warpReduceMax(v);
        if (tid == 0) red[0] = v;
    }
    __syncthreads();
    const float M = red[0];
    __syncthreads();

    float s = 0.f;
#pragma unroll
    for (int j = 0; j < 8; j++) {
        float e = (base + j < n) ? __expf(r[j] - M) : 0.f;
        r[j] = e;
        s += e;
    }
    s = warpReduceSum(s);
    if ((tid & 31) == 0) red[tid >> 5] = s;
    __syncthreads();
    {
        float v = (tid < 8) ? red[tid] : 0.f;
        v = warpReduceSum(v);
        if (tid == 0) red[0] = v;
    }
    __syncthreads();
    const float inv = 1.0f / red[0];

    a.x = r[0] * inv; a.y = r[1] * inv; a.z = r[2] * inv; a.w = r[3] * inv;
    b2.x = r[4] * inv; b2.y = r[5] * inv; b2.z = r[6] * inv; b2.w = r[7] * inv;
    *(float4*)(row + base) = a;
    *(float4*)(row + base + 4) = b2;
}

// ---------------- PV: Y = P @ V, 128q x 64d tiles ----------------
__global__ __launch_bounds__(256) void attn_pv_f16(
    const float* __restrict__ att, const h16* __restrict__ Vth,
    h16* __restrict__ Yh, h16* __restrict__ Yl)
{
    const int qb = (gridDim.x - 1) - blockIdx.x;   // heavy blocks first
    const int z  = blockIdx.y;
    const int b   = z >> 4;
    const int g   = (z >> 2) & 3;
    const int hkv = z & 3;

    extern __shared__ h16 sm[];
    h16 (*sPh)[72] = (h16(*)[72])sm;
    h16 (*sPl)[72] = (h16(*)[72])(sm + 128 * 72);
    h16 (*sVh)[72] = (h16(*)[72])(sm + 2 * 128 * 72);

    const int tid  = threadIdx.x;
    const int w    = tid >> 5, lane = tid & 31;
    const int lg   = lane >> 2, tg = lane & 3;
    const int m0   = (w & 3) * 32;
    const int n0   = (w >> 2) * 32;

    const int prow = tid >> 1;
    const int pc   = (tid & 1) * 32;
    const int vrow = tid >> 2;
    const int vc   = (tid & 3) * 16;

    float acc[2][4][4];
#pragma unroll
    for (int i = 0; i < 2; i++)
#pragma unroll
        for (int j = 0; j < 4; j++)
#pragma unroll
            for (int v = 0; v < 4; v++) acc[i][j][v] = 0.f;

    const float* attrow = att + ((size_t)z * TT + qb * 128 + prow) * TT + pc;
    const h16* vbh = Vth + (size_t)(b * KVW + hkv * 64 + vrow) * TT + vc;

    const int nkb = 2 * qb + 2;
    for (int kb = 0; kb < nkb; kb++) {
#pragma unroll
        for (int v = 0; v < 8; v++) {
            float4 p = *(const float4*)(attrow + kb * 64 + v * 4);
            h16 h0, l0, h1, l1, h2, l2, h3, l3;
            hsplit(p.x, h0, l0); hsplit(p.y, h1, l1);
            hsplit(p.z, h2, l2); hsplit(p.w, h3, l3);
            __half2 t;
            t.x = h0; t.y = h1; *(__half2*)&sPh[prow][pc + v * 4] = t;
            t.x = h2; t.y = h3; *(__half2*)&sPh[prow][pc + v * 4 + 2] = t;
            t.x = l0; t.y = l1; *(__half2*)&sPl[prow][pc + v * 4] = t;
            t.x = l2; t.y = l3; *(__half2*)&sPl[prow][pc + v * 4 + 2] = t;
        }
        *(uint4*)&sVh[vrow][vc]     = *(const uint4*)(vbh + kb * 64);
        *(uint4*)&sVh[vrow][vc + 8] = *(const uint4*)(vbh + kb * 64 + 8);
        __syncthreads();

#pragma unroll
        for (int kk = 0; kk < 64; kk += 16) {
            uint32_t ah[2][4], al[2][4], bh[4][2];
#pragma unroll
            for (int mt = 0; mt < 2; mt++) {
                const int r = m0 + mt * 16 + lg;
                ah[mt][0] = *(const uint32_t*)&sPh[r][kk + tg * 2];
                ah[mt][1] = *(const uint32_t*)&sPh[r + 8][kk + tg * 2];
                ah[mt][2] = *(const uint32_t*)&sPh[r][kk + tg * 2 + 8];
                ah[mt][3] = *(const uint32_t*)&sPh[r + 8][kk + tg * 2 + 8];
                al[mt][0] = *(const uint32_t*)&sPl[r][kk + tg * 2];
                al[mt][1] = *(const uint32_t*)&sPl[r + 8][kk + tg * 2];
                al[mt][2] = *(const uint32_t*)&sPl[r][kk + tg * 2 + 8];
                al[mt][3] = *(const uint32_t*)&sPl[r + 8][kk + tg * 2 + 8];
            }
#pragma unroll
            for (int nt = 0; nt < 4; nt++) {
                const int n = n0 + nt * 8 + lg;
                bh[nt][0] = *(const uint32_t*)&sVh[n][kk + tg * 2];
                bh[nt][1] = *(const uint32_t*)&sVh[n][kk + tg * 2 + 8];
            }
#pragma unroll
            for (int mt = 0; mt < 2; mt++)
#pragma unroll
                for (int nt = 0; nt < 4; nt++) {
                    mma_f16(acc[mt][nt], ah[mt][0], ah[mt][1], ah[mt][2], ah[mt][3],
                            bh[nt][0], bh[nt][1]);
                    mma_f16(acc[mt][nt], al[mt][0], al[mt][1], al[mt][2], al[mt][3],
                            bh[nt][0], bh[nt][1]);
                }
        }
        __syncthreads();
    }

    const int colbase = hkv * 256 + g * 64;
#pragma unroll
    for (int mt = 0; mt < 2; mt++)
#pragma unroll
        for (int nt = 0; nt < 4; nt++) {
            const int col = colbase + n0 + nt * 8 + 2 * tg;
            const int r0 = b * TT + qb * 128 + m0 + mt * 16 + lg;
            h16 h0, l0, h1, l1;
            __half2 t;
            hsplit(acc[mt][nt][0], h0, l0); hsplit(acc[mt][nt][1], h1, l1);
            t.x = h0; t.y = h1; *(__half2*)&Yh[(size_t)r0 * EE + col] = t;
            t.x = l0; t.y = l1; *(__half2*)&Yl[(size_t)r0 * EE + col] = t;
            hsplit(acc[mt][nt][2], h0, l0); hsplit(acc[mt][nt][3], h1, l1);
            t.x = h0; t.y = h1; *(__half2*)&Yh[(size_t)(r0 + 8) * EE + col] = t;
            t.x = l0; t.y = l1; *(__half2*)&Yl[(size_t)(r0 + 8) * EE + col] = t;
        }
}

// ---------------- launch ----------------
extern "C" void kernel_launch(void* const* d_in, const int* in_sizes, int n_in,
                              void* d_out, int out_size)
{
    const float* x  = (const float*)d_in[0];
    const float* Wq = (const float*)d_in[2];
    const float* bq = (const float*)d_in[3];
    const float* Wk = (const float*)d_in[4];
    const float* bk = (const float*)d_in[5];
    const float* Wv = (const float*)d_in[6];
    const float* bv = (const float*)d_in[7];
    const float* Wo = (const float*)d_in[8];
    const float* bo = (const float*)d_in[9];
    float* out = (float*)d_out;

    float *Qb, *Kb, *Vb, *attScratch;
    h16 *xh, *xl, *Qh, *Ql, *Kh, *Kl, *Vth, *Yh, *Yl;
    h16 *Wqth, *Wkth, *Wvth, *Woth;
    cudaGetSymbolAddress((void**)&Qb, g_Q);
    cudaGetSymbolAddress((void**)&Kb, g_K);
    cudaGetSymbolAddress((void**)&Vb, g_V);
    cudaGetSymbolAddress((void**)&attScratch, g_Att);
    cudaGetSymbolAddress((void**)&xh, g_xh);
    cudaGetSymbolAddress((void**)&xl, g_xl);
    cudaGetSymbolAddress((void**)&Qh, g_Qh);
    cudaGetSymbolAddress((void**)&Ql, g_Ql);
    cudaGetSymbolAddress((void**)&Kh, g_Kh);
    cudaGetSymbolAddress((void**)&Kl, g_Kl);
    cudaGetSymbolAddress((void**)&Vth, g_Vth);
    cudaGetSymbolAddress((void**)&Yh, g_Yh);
    cudaGetSymbolAddress((void**)&Yl, g_Yl);
    cudaGetSymbolAddress((void**)&Wqth, g_Wqth);
    cudaGetSymbolAddress((void**)&Wkth, g_Wkth);
    cudaGetSymbolAddress((void**)&Wvth, g_Wvth);
    cudaGetSymbolAddress((void**)&Woth, g_Woth);

    float* att = ((size_t)out_size >= Y_ELEMS + ATT_ELEMS) ? (out + Y_ELEMS)
                                                           : attScratch;

    const int SMEM_SC = 3 * 128 * 72 * (int)sizeof(h16);            // 55296
    const int SMEM_PV = (2 * 128 + 64) * 72 * (int)sizeof(h16);     // 46080
    cudaFuncSetAttribute(attn_scores_f16, cudaFuncAttributeMaxDynamicSharedMemorySize, SMEM_SC);
    cudaFuncSetAttribute(attn_pv_f16,    cudaFuncAttributeMaxDynamicSharedMemorySize, SMEM_PV);

    // 0) weight transpose+convert, x split
    wtrans_half<<<dim3(EE / 32, EE / 32),  dim3(32, 8)>>>(Wq, Wqth, EE, EE);
    wtrans_half<<<dim3(KVW / 32, EE / 32), dim3(32, 8)>>>(Wk, Wkth, EE, KVW);
    wtrans_half<<<dim3(KVW / 32, EE / 32), dim3(32, 8)>>>(Wv, Wvth, EE, KVW);
    wtrans_half<<<dim3(EE / 32, EE / 32),  dim3(32, 8)>>>(Wo, Woth, EE, EE);
    split_x<<<(ROWS * EE / 4 + 255) / 256, 256>>>((const float4*)x, xh, xl, ROWS * EE / 4);

    // 1) projections
    gemm2p<<<dim3(EE / 128, ROWS / 128), 256>>>(xh, xl, Wqth, bq, Qb, ROWS, EE, EE);
    gemm2p_kv<<<dim3(KVW / 128, ROWS / 128, 2), 256>>>(xh, xl, Wkth, bk, Kb, Wvth, bv, Vb);

    // 2) RoPE + split; V transpose+convert
    rope_split<<<(ROWS * HQn * 32) / 256, 256>>>(Qb, Qh, Ql, HQn);
    rope_split<<<(ROWS * HKVn * 32) / 256, 256>>>(Kb, Kh, Kl, HKVn);
    vtrans_half<<<dim3(KVW / 32, ROWS / 32), dim3(32, 8)>>>(Vb, Vth);

    // 3) scores (triangular grid, 128x128 tiles)
    attn_scores_f16<<<dim3(16 * 17 / 2, BB * HQn), 256, SMEM_SC>>>(Qh, Ql, Kh, att);

    // 4) softmax
    softmax_vec<<<dim3(TT, BB * HQn), 256>>>(att);

    // 5) PV -> Yh/Yl
    attn_pv_f16<<<dim3(TT / 128, BB * HQn), 256, SMEM_PV>>>(att, Vth, Yh, Yl);

    // 6) output projection
    gemm2p<<<dim3(EE / 128, ROWS / 128), 256>>>(Yh, Yl, Woth, bo, out, ROWS, EE, EE);
}